// round 6
// baseline (speedup 1.0000x reference)
#include <cuda_runtime.h>
#include <cstdint>
#include <cstddef>

// ---------------------------------------------------------------------------
// myVMLSTM: T=256, B=64, D=1024, H=1024, R=256
//   precompute:  d2 = diag - lowrank-diag correction; Gx = (X u_x) w_x^T + x*d2 + b
//   recurrence:  persistent kernel, 128 CTAs, 512 thr, grid barrier, FFMA2
// ---------------------------------------------------------------------------

constexpr int T   = 256;
constexpr int Bsz = 64;
constexpr int D   = 1024;
constexpr int H   = 1024;
constexpr int R   = 256;
constexpr int G4H = 4 * H;          // 4096
constexpr int TB  = T * Bsz;        // 16384
constexpr int NB  = 128;            // persistent blocks
constexpr int NTH = 512;

// scratch (static __device__ arrays: allocation-free per harness rules)
__device__ float g_P [(size_t)TB * R];     // 16 MB   X @ u_x
__device__ float g_Gx[(size_t)TB * G4H];   // 256 MB  precomputed input-path gates
__device__ float g_d2x[G4H];
__device__ float g_d2h[G4H];
__device__ float g_h [Bsz * H];            // current hidden state
__device__ float g_p [Bsz * R];            // per-step h @ u_h
__device__ unsigned g_count;
__device__ unsigned g_phase;

// ---------------------------------------------------------------------------
// packed fp32x2 helpers (Blackwell FFMA2 — ptxas never auto-emits this)
// ---------------------------------------------------------------------------
__device__ __forceinline__ void fma2(unsigned long long& acc,
                                     unsigned long long a, unsigned long long b) {
    asm("fma.rn.f32x2 %0, %1, %2, %0;" : "+l"(acc) : "l"(a), "l"(b));
}
__device__ __forceinline__ unsigned long long pack_dup(float a) {
    unsigned long long v;
    asm("mov.b64 %0, {%1, %1};" : "=l"(v) : "f"(a));
    return v;
}
__device__ __forceinline__ float2 unpack2(unsigned long long v) {
    float2 f;
    asm("mov.b64 {%0, %1}, %2;" : "=f"(f.x), "=f"(f.y) : "l"(v));
    return f;
}

// ---------------------------------------------------------------------------
// grid barrier (all NB blocks resident by construction)
// ---------------------------------------------------------------------------
__device__ __forceinline__ void gbar() {
    __threadfence();
    __syncthreads();
    if (threadIdx.x == 0) {
        unsigned my = *(volatile unsigned*)&g_phase;
        if (atomicAdd(&g_count, 1u) == NB - 1) {
            g_count = 0u;
            __threadfence();
            *(volatile unsigned*)&g_phase = my + 1u;
        } else {
            while (*(volatile unsigned*)&g_phase == my) { }
        }
        __threadfence();
    }
    __syncthreads();
}

// ---------------------------------------------------------------------------
// prep: d2[n] = dia[n%H] - sum_r u[d,r] w[n,r]  (x and h), copy h0 -> g_h
// ---------------------------------------------------------------------------
__global__ void prep_kernel(const float* __restrict__ u_x, const float* __restrict__ w_x,
                            const float* __restrict__ dia_x,
                            const float* __restrict__ u_h, const float* __restrict__ w_h,
                            const float* __restrict__ dia_h,
                            const float* __restrict__ h0)
{
    int n = blockIdx.x * blockDim.x + threadIdx.x;   // 0..8191
    const float *u, *w, *dia; float* o; int idx;
    if (n < G4H) { u = u_x; w = w_x; dia = dia_x; o = g_d2x; idx = n; }
    else         { u = u_h; w = w_h; dia = dia_h; o = g_d2h; idx = n - G4H; }
    int d = idx & (H - 1);
    const float4* ur = reinterpret_cast<const float4*>(u + (size_t)d   * R);
    const float4* wr = reinterpret_cast<const float4*>(w + (size_t)idx * R);
    float s = 0.f;
    #pragma unroll 8
    for (int k = 0; k < R / 4; ++k) {
        float4 a = ur[k], b = wr[k];
        s += a.x * b.x + a.y * b.y + a.z * b.z + a.w * b.w;
    }
    o[idx] = dia[d] - s;
    for (int i = n; i < Bsz * H; i += 8192) g_h[i] = h0[i];
}

// ---------------------------------------------------------------------------
// tiled fp32 GEMM (FFMA2 + double-buffered SMEM), C[M,N] = sum_k A[m,k]*B(k,n)
//   B_IS_NK: B stored [N,K] row-major (for w_x) else [K,N] (for u_x)
//   EPI:     C += X[m, n&1023]*d2[n] + bias[n]
// ---------------------------------------------------------------------------
template<bool B_IS_NK, bool EPI>
__global__ void __launch_bounds__(256, 2) gemm_k(
    const float* __restrict__ A, const float* __restrict__ Bm, float* __restrict__ C,
    int M, int N, int K,
    const float* __restrict__ X, const float* __restrict__ d2v, const float* __restrict__ bias)
{
    constexpr int BM = 128, BN = 128, BK = 16;
    __shared__ float As[2][BK][BM];
    __shared__ float Bs[2][BK][BN];
    const int tid = threadIdx.x;
    const int m0 = blockIdx.y * BM, n0 = blockIdx.x * BN;
    const int tx = tid & 15, ty = tid >> 4;

    unsigned long long acc2[8][4];
    #pragma unroll
    for (int i = 0; i < 8; ++i)
        #pragma unroll
        for (int j = 0; j < 4; ++j) acc2[i][j] = 0ull;

    float4 ra[2], rb[2];

    auto ldg_tiles = [&](int k0) {
        #pragma unroll
        for (int q = 0; q < 2; ++q) {
            int f = tid * 2 + q;
            { int row = f >> 2, kq = f & 3;
              ra[q] = *reinterpret_cast<const float4*>(
                  &A[(size_t)(m0 + row) * K + k0 + kq * 4]); }
            if constexpr (B_IS_NK) {
                int row = f >> 2, kq = f & 3;
                rb[q] = *reinterpret_cast<const float4*>(
                    &Bm[(size_t)(n0 + row) * K + k0 + kq * 4]);
            } else {
                int kr = f >> 5, nc = f & 31;
                rb[q] = *reinterpret_cast<const float4*>(
                    &Bm[(size_t)(k0 + kr) * N + n0 + nc * 4]);
            }
        }
    };
    auto sts_tiles = [&](int buf) {
        #pragma unroll
        for (int q = 0; q < 2; ++q) {
            int f = tid * 2 + q;
            { int row = f >> 2, kq = f & 3;
              As[buf][kq * 4 + 0][row] = ra[q].x;
              As[buf][kq * 4 + 1][row] = ra[q].y;
              As[buf][kq * 4 + 2][row] = ra[q].z;
              As[buf][kq * 4 + 3][row] = ra[q].w; }
            if constexpr (B_IS_NK) {
                int row = f >> 2, kq = f & 3;
                Bs[buf][kq * 4 + 0][row] = rb[q].x;
                Bs[buf][kq * 4 + 1][row] = rb[q].y;
                Bs[buf][kq * 4 + 2][row] = rb[q].z;
                Bs[buf][kq * 4 + 3][row] = rb[q].w;
            } else {
                int kr = f >> 5, nc = f & 31;
                *reinterpret_cast<float4*>(&Bs[buf][kr][nc * 4]) = rb[q];
            }
        }
    };

    ldg_tiles(0);
    sts_tiles(0);
    __syncthreads();

    const int nIter = K / BK;
    for (int it = 0; it < nIter; ++it) {
        const int cur = it & 1;
        if (it + 1 < nIter) ldg_tiles((it + 1) * BK);
        #pragma unroll
        for (int k = 0; k < BK; ++k) {
            float af[8];
            *reinterpret_cast<float4*>(af)     =
                *reinterpret_cast<const float4*>(&As[cur][k][ty * 8]);
            *reinterpret_cast<float4*>(af + 4) =
                *reinterpret_cast<const float4*>(&As[cur][k][ty * 8 + 4]);
            ulonglong2 b01 = *reinterpret_cast<const ulonglong2*>(&Bs[cur][k][tx * 8]);
            ulonglong2 b23 = *reinterpret_cast<const ulonglong2*>(&Bs[cur][k][tx * 8 + 4]);
            #pragma unroll
            for (int i = 0; i < 8; ++i) {
                unsigned long long ai = pack_dup(af[i]);
                fma2(acc2[i][0], ai, b01.x);
                fma2(acc2[i][1], ai, b01.y);
                fma2(acc2[i][2], ai, b23.x);
                fma2(acc2[i][3], ai, b23.y);
            }
        }
        if (it + 1 < nIter) sts_tiles(cur ^ 1);
        __syncthreads();
    }

    #pragma unroll
    for (int i = 0; i < 8; ++i) {
        int m = m0 + ty * 8 + i;
        float vf[8];
        #pragma unroll
        for (int jp = 0; jp < 4; ++jp) {
            float2 f = unpack2(acc2[i][jp]);
            vf[jp * 2] = f.x; vf[jp * 2 + 1] = f.y;
        }
        #pragma unroll
        for (int jj = 0; jj < 2; ++jj) {
            int n = n0 + tx * 8 + jj * 4;
            float4 v;
            v.x = vf[jj * 4 + 0]; v.y = vf[jj * 4 + 1];
            v.z = vf[jj * 4 + 2]; v.w = vf[jj * 4 + 3];
            if constexpr (EPI) {
                const float* xr = &X[(size_t)m * H];
                v.x += xr[(n + 0) & (H - 1)] * d2v[n + 0] + bias[n + 0];
                v.y += xr[(n + 1) & (H - 1)] * d2v[n + 1] + bias[n + 1];
                v.z += xr[(n + 2) & (H - 1)] * d2v[n + 2] + bias[n + 2];
                v.w += xr[(n + 3) & (H - 1)] * d2v[n + 3] + bias[n + 3];
            }
            *reinterpret_cast<float4*>(&C[(size_t)m * N + n]) = v;
        }
    }
}

// ---------------------------------------------------------------------------
// persistent recurrent kernel, 128 CTAs x 512 threads
//   phase1: CTA (rb=bk&15, bb=bk>>4) computes p[8 b-rows, 16 r-cols];
//           u_h slice (16 cols) persistent in SMEM; only 8 h-rows read/step
//   phase2: CTA bk owns h cols [8bk..8bk+8); thread = (batch b2, col jl2)
// ---------------------------------------------------------------------------
constexpr int SU_ST = 1028;                     // pad vs bank conflicts
constexpr int SU_F  = 16 * SU_ST;               // 16448
constexpr int SW_ST = 260;
constexpr int SW_F  = 32 * SW_ST;               // 8320
constexpr int RED_F = 512;
constexpr int SB_F  = 64 * 260;                 // 16640
constexpr int SMEM_F = SU_F + SW_F + RED_F + SB_F;   // 41920 floats
constexpr size_t SMEM_BYTES = (size_t)SMEM_F * 4;    // 167680 B

__global__ void __launch_bounds__(NTH, 1) lstm_rec(
    const float* __restrict__ c0, const float* __restrict__ h0,
    const float* __restrict__ u_h, const float* __restrict__ w_h,
    const float* __restrict__ b_h, float* __restrict__ out, int full_out)
{
    extern __shared__ float sm[];
    float* su   = sm;                 // [16][1028] this CTA's u_h columns
    float* swt  = sm + SU_F;          // [32][260]  this CTA's w_h rows (4g x 8j)
    float* red  = swt + SW_F;         // [512]
    float* sbuf = red + RED_F;        // phase1: h stage [8][1028]; phase2: p [64][260]

    const int tid = threadIdx.x;
    const int bk  = blockIdx.x;

    // phase1 roles
    const int rb  = bk & 15,  bb = bk >> 4;
    const int r_l = tid & 15, b_l = (tid >> 4) & 7, q = tid >> 7;
    // phase2 roles
    const int jl2 = tid & 7,  b2 = tid >> 3;
    const int j   = bk * 8 + jl2;

    // persistent SMEM (once for all 256 steps)
    for (int i = tid; i < 16 * 1024; i += NTH) {
        int rl = i >> 10, d = i & 1023;
        su[rl * SU_ST + d] = u_h[(size_t)d * R + rb * 16 + rl];
    }
    for (int i = tid; i < 32 * 256; i += NTH) {
        int row = i >> 8, r = i & 255;
        int g = row >> 3, jj = row & 7;
        swt[row * SW_ST + r] = w_h[(size_t)(g * H + bk * 8 + jj) * R + r];
    }

    // per-thread state (b2, j) for all 256 steps
    float d2r[4], bhr[4];
    #pragma unroll
    for (int g = 0; g < 4; ++g) {
        d2r[g] = g_d2h[g * H + j];
        bhr[g] = b_h[g * H + j];
    }
    float hr = h0[b2 * H + j];
    float cr = c0[b2 * H + j];
    __syncthreads();

    for (int t = 0; t < T; ++t) {
        // ------------- phase 1: p[8b,16r] = h[8b,:] @ u_h[:,16r] -----------
        for (int i = tid; i < 8 * 256; i += NTH) {          // stage 8 h rows
            int row = i >> 8, c = i & 255;
            *reinterpret_cast<float4*>(&sbuf[row * SU_ST + c * 4]) =
                __ldcg(reinterpret_cast<const float4*>(
                    &g_h[(bb * 8 + row) * H + c * 4]));
        }
        __syncthreads();
        {
            unsigned long long a0 = 0ull, a1 = 0ull;
            const ulonglong2* hp =
                reinterpret_cast<const ulonglong2*>(&sbuf[b_l * SU_ST + q * 256]);
            const ulonglong2* up =
                reinterpret_cast<const ulonglong2*>(&su[r_l * SU_ST + q * 256]);
            #pragma unroll 8
            for (int k = 0; k < 64; ++k) {
                ulonglong2 hh = hp[k], uu = up[k];
                fma2(a0, hh.x, uu.x);
                fma2(a1, hh.y, uu.y);
            }
            float2 f0 = unpack2(a0), f1 = unpack2(a1);
            red[tid] = (f0.x + f0.y) + (f1.x + f1.y);
        }
        __syncthreads();
        if (tid < 128) {
            float s = red[tid] + red[tid + 128] + red[tid + 256] + red[tid + 384];
            int b = bb * 8 + (tid >> 4), r = rb * 16 + (tid & 15);
            __stcg(&g_p[b * R + r], s);
        }
        gbar();

        // ------------- phase 2: gates + state update -----------------------
        const float* gp = g_Gx + (size_t)t * (Bsz * G4H) + (size_t)b2 * G4H + j;
        float gx0 = __ldcs(gp);
        float gx1 = __ldcs(gp + H);
        float gx2 = __ldcs(gp + 2 * H);
        float gx3 = __ldcs(gp + 3 * H);

        for (int i = tid; i < 64 * 64; i += NTH) {          // stage p [64][256]
            int bbx = i >> 6, c = i & 63;
            *reinterpret_cast<float4*>(&sbuf[bbx * 260 + c * 4]) =
                __ldcg(reinterpret_cast<const float4*>(g_p) + i);
        }
        __syncthreads();

        unsigned long long A0 = 0, A1 = 0, B0 = 0, B1 = 0,
                           C0 = 0, C1 = 0, D0 = 0, D1 = 0;
        {
            const ulonglong2* pp =
                reinterpret_cast<const ulonglong2*>(&sbuf[b2 * 260]);
            const ulonglong2* w0 =
                reinterpret_cast<const ulonglong2*>(&swt[(0 * 8 + jl2) * SW_ST]);
            const ulonglong2* w1 =
                reinterpret_cast<const ulonglong2*>(&swt[(1 * 8 + jl2) * SW_ST]);
            const ulonglong2* w2 =
                reinterpret_cast<const ulonglong2*>(&swt[(2 * 8 + jl2) * SW_ST]);
            const ulonglong2* w3 =
                reinterpret_cast<const ulonglong2*>(&swt[(3 * 8 + jl2) * SW_ST]);
            #pragma unroll 8
            for (int k = 0; k < 64; ++k) {
                ulonglong2 pv = pp[k];
                ulonglong2 w;
                w = w0[k]; fma2(A0, pv.x, w.x); fma2(A1, pv.y, w.y);
                w = w1[k]; fma2(B0, pv.x, w.x); fma2(B1, pv.y, w.y);
                w = w2[k]; fma2(C0, pv.x, w.x); fma2(C1, pv.y, w.y);
                w = w3[k]; fma2(D0, pv.x, w.x); fma2(D1, pv.y, w.y);
            }
        }
        float2 fa0 = unpack2(A0), fa1 = unpack2(A1);
        float2 fb0 = unpack2(B0), fb1 = unpack2(B1);
        float2 fc0 = unpack2(C0), fc1 = unpack2(C1);
        float2 fd0 = unpack2(D0), fd1 = unpack2(D1);
        float pi = (fa0.x + fa0.y) + (fa1.x + fa1.y) + hr * d2r[0] + bhr[0] + gx0;
        float pf = (fb0.x + fb0.y) + (fb1.x + fb1.y) + hr * d2r[1] + bhr[1] + gx1;
        float po = (fc0.x + fc0.y) + (fc1.x + fc1.y) + hr * d2r[2] + bhr[2] + gx2;
        float pn = (fd0.x + fd0.y) + (fd1.x + fd1.y) + hr * d2r[3] + bhr[3] + gx3;

        float ig = 1.f / (1.f + expf(-pi));
        float fg = 1.f / (1.f + expf(-pf));
        float og = 1.f / (1.f + expf(-po));
        float ng = tanhf(pn);
        cr = fg * cr + ig * ng;
        hr = og * tanhf(cr);

        __stcg(&g_h[b2 * H + j], hr);
        __stcs(&out[(size_t)t * (Bsz * H) + b2 * H + j], hr);
        if (t == T - 1 && full_out) {
            out[(size_t)T * Bsz * H + b2 * H + j]           = hr;
            out[(size_t)T * Bsz * H + Bsz * H + b2 * H + j] = cr;
        }
        gbar();
    }
}

// ---------------------------------------------------------------------------
extern "C" void kernel_launch(void* const* d_in, const int* in_sizes, int n_in,
                              void* d_out, int out_size)
{
    const float* x     = (const float*)d_in[0];
    const float* h0    = (const float*)d_in[1];
    const float* c0    = (const float*)d_in[2];
    const float* u_x   = (const float*)d_in[3];
    const float* u_h   = (const float*)d_in[4];
    const float* w_x   = (const float*)d_in[5];
    const float* w_h   = (const float*)d_in[6];
    const float* b_x   = (const float*)d_in[7];
    const float* b_h   = (const float*)d_in[8];
    const float* dia_x = (const float*)d_in[9];
    const float* dia_h = (const float*)d_in[10];
    float* out = (float*)d_out;

    float *pP = nullptr, *pGx = nullptr, *pd2x = nullptr;
    cudaGetSymbolAddress((void**)&pP,   g_P);
    cudaGetSymbolAddress((void**)&pGx,  g_Gx);
    cudaGetSymbolAddress((void**)&pd2x, g_d2x);

    // 1) diag corrections + h init
    prep_kernel<<<32, 256>>>(u_x, w_x, dia_x, u_h, w_h, dia_h, h0);

    // 2) P = X @ u_x      (M=16384, N=256, K=1024; B stored [K,N])
    {
        dim3 grid(R / 128, TB / 128);
        gemm_k<false, false><<<grid, 256>>>(x, u_x, pP, TB, R, D,
                                            nullptr, nullptr, nullptr);
    }
    // 3) Gx = P @ w_x^T + x*d2_x + b_x   (M=16384, N=4096, K=256; B stored [N,K])
    {
        dim3 grid(G4H / 128, TB / 128);
        gemm_k<true, true><<<grid, 256>>>(pP, w_x, pGx, TB, G4H, R,
                                          x, pd2x, b_x);
    }
    // 4) persistent recurrence
    cudaFuncSetAttribute(lstm_rec, cudaFuncAttributeMaxDynamicSharedMemorySize,
                         (int)SMEM_BYTES);
    int full_out = (out_size >= T * Bsz * H + 2 * Bsz * H) ? 1 : 0;
    lstm_rec<<<NB, NTH, SMEM_BYTES>>>(c0, h0, u_h, w_h, b_h, out, full_out);
}

// round 9
// speedup vs baseline: 1.1024x; 1.1024x over previous
#include <cuda_runtime.h>
#include <cuda_bf16.h>
#include <cstdint>
#include <cstddef>

constexpr int T=256, Bsz=64, D=1024, H=1024, R=256;
constexpr int G4H=4*H, TB=T*Bsz, NB=128, NTH=512;

// static scratch (allocation-free)
// packed 3-pass layouts: A' = [hi | lo | hi], B' = [hi | hi | lo] along K
__device__ __align__(256) __nv_bfloat16 g_Xp[(size_t)TB*3*D];    // X'  [TB, 3072]
__device__ __align__(256) __nv_bfloat16 g_Wp[(size_t)G4H*3*R];   // Wx' [4096, 768]
__device__ __align__(256) __nv_bfloat16 g_Up[(size_t)R*3*D];     // UxT'[256, 3072]
__device__ __align__(256) __nv_bfloat16 g_Pp[(size_t)TB*3*R];    // P'  [TB, 768]
__device__ float g_Gx[(size_t)TB*G4H];
__device__ float g_d2x[G4H];
__device__ float g_d2h[G4H];
__device__ float g_h[Bsz*H];
__device__ float g_p[Bsz*R];
__device__ unsigned g_count;
__device__ unsigned g_phase;

// ---------------- helpers ----------------
__device__ __forceinline__ void fma2(unsigned long long& acc,
                                     unsigned long long a, unsigned long long b) {
    asm("fma.rn.f32x2 %0, %1, %2, %0;" : "+l"(acc) : "l"(a), "l"(b));
}
__device__ __forceinline__ float2 unpack2(unsigned long long v) {
    float2 f; asm("mov.b64 {%0, %1}, %2;" : "=f"(f.x), "=f"(f.y) : "l"(v)); return f;
}
__device__ __forceinline__ uint32_t smem_u32(const void* p) {
    uint32_t a;
    asm("{ .reg .u64 t; cvta.to.shared.u64 t, %1; cvt.u32.u64 %0, t; }" : "=r"(a) : "l"(p));
    return a;
}
__device__ __forceinline__ void cp16(uint32_t dst, const void* src) {
    asm volatile("cp.async.cg.shared.global [%0], [%1], 16;" :: "r"(dst), "l"(src) : "memory");
}
__device__ __forceinline__ uint32_t swz(uint32_t o) { return o ^ ((o >> 3) & 0x70); }

__device__ __forceinline__ void ldsm4(uint32_t* r, uint32_t addr) {
    asm volatile("ldmatrix.sync.aligned.m8n8.x4.shared.b16 {%0,%1,%2,%3}, [%4];"
        : "=r"(r[0]), "=r"(r[1]), "=r"(r[2]), "=r"(r[3]) : "r"(addr));
}
__device__ __forceinline__ void mma16816(float* c, const uint32_t* a,
                                         uint32_t b0, uint32_t b1) {
    asm volatile(
        "mma.sync.aligned.m16n8k16.row.col.f32.bf16.bf16.f32 "
        "{%0,%1,%2,%3}, {%4,%5,%6,%7}, {%8,%9}, {%0,%1,%2,%3};"
        : "+f"(c[0]), "+f"(c[1]), "+f"(c[2]), "+f"(c[3])
        : "r"(a[0]), "r"(a[1]), "r"(a[2]), "r"(a[3]), "r"(b0), "r"(b1));
}

// ---------------- grid barrier ----------------
__device__ __forceinline__ void gbar() {
    __threadfence();
    __syncthreads();
    if (threadIdx.x == 0) {
        unsigned my = *(volatile unsigned*)&g_phase;
        if (atomicAdd(&g_count, 1u) == NB - 1) {
            g_count = 0u; __threadfence();
            *(volatile unsigned*)&g_phase = my + 1u;
        } else {
            while (*(volatile unsigned*)&g_phase == my) { }
        }
        __threadfence();
    }
    __syncthreads();
}

// ---------------- conversions ----------------
// rows of (1<<ls) fp32 -> rows of 3*(1<<ls) bf16 laid out [hi | lo | hi]
__global__ void conv_pack(const float* __restrict__ s, __nv_bfloat16* __restrict__ d,
                          int ls, int n4)
{
    const int rl = 1 << ls, mask = rl - 1;
    for (int i = blockIdx.x*blockDim.x + threadIdx.x; i < n4; i += gridDim.x*blockDim.x) {
        float4 v = reinterpret_cast<const float4*>(s)[i];
        int e = i * 4, m = e >> ls, col = e & mask;
        __nv_bfloat16 h0=__float2bfloat16(v.x), h1=__float2bfloat16(v.y);
        __nv_bfloat16 h2=__float2bfloat16(v.z), h3=__float2bfloat16(v.w);
        __nv_bfloat162 ha{h0,h1}, hb{h2,h3};
        __nv_bfloat162 la{__float2bfloat16(v.x-__bfloat162float(h0)),
                          __float2bfloat16(v.y-__bfloat162float(h1))};
        __nv_bfloat162 lb{__float2bfloat16(v.z-__bfloat162float(h2)),
                          __float2bfloat16(v.w-__bfloat162float(h3))};
        __nv_bfloat16* rp = d + (size_t)m*3*rl + col;
        reinterpret_cast<__nv_bfloat162*>(rp)[0]        = ha;
        reinterpret_cast<__nv_bfloat162*>(rp)[1]        = hb;
        reinterpret_cast<__nv_bfloat162*>(rp + rl)[0]   = la;
        reinterpret_cast<__nv_bfloat162*>(rp + rl)[1]   = lb;
        reinterpret_cast<__nv_bfloat162*>(rp + 2*rl)[0] = ha;
        reinterpret_cast<__nv_bfloat162*>(rp + 2*rl)[1] = hb;
    }
}
// u_x [D,R] fp32 -> UxT' [R, 3D] bf16, layout per row: [hi(D) | lo(D) | hi(D)]
// NOTE: B' side gets [hi | hi | lo] ordering; the A' side carries [hi | lo | hi].
// For GEMM1, A' = X' ([hi|lo|hi]) and B' = U' must be [hi|hi|lo].
__global__ void conv_uT(const float* __restrict__ u, __nv_bfloat16* __restrict__ d)
{
    for (int i = blockIdx.x*blockDim.x + threadIdx.x; i < R*D; i += gridDim.x*blockDim.x) {
        int n = i >> 10, dd = i & 1023;
        float v = u[(size_t)dd*R + n];
        __nv_bfloat16 h = __float2bfloat16(v);
        __nv_bfloat16 l = __float2bfloat16(v - __bfloat162float(h));
        d[(size_t)n*3*D + dd]       = h;    // segment 0: hi (pairs with X hi)
        d[(size_t)n*3*D + D + dd]   = h;    // segment 1: hi (pairs with X lo)
        d[(size_t)n*3*D + 2*D + dd] = l;    // segment 2: lo (pairs with X hi)
    }
}
// w_x [4096,256] fp32 -> Wx' [4096, 768], layout per row: [hi | hi | lo]
__global__ void conv_wB(const float* __restrict__ w, __nv_bfloat16* __restrict__ d)
{
    for (int i = blockIdx.x*blockDim.x + threadIdx.x; i < G4H*R/4; i += gridDim.x*blockDim.x) {
        float4 v = reinterpret_cast<const float4*>(w)[i];
        int e = i * 4, m = e >> 8, col = e & 255;
        __nv_bfloat16 h0=__float2bfloat16(v.x), h1=__float2bfloat16(v.y);
        __nv_bfloat16 h2=__float2bfloat16(v.z), h3=__float2bfloat16(v.w);
        __nv_bfloat162 ha{h0,h1}, hb{h2,h3};
        __nv_bfloat162 la{__float2bfloat16(v.x-__bfloat162float(h0)),
                          __float2bfloat16(v.y-__bfloat162float(h1))};
        __nv_bfloat162 lb{__float2bfloat16(v.z-__bfloat162float(h2)),
                          __float2bfloat16(v.w-__bfloat162float(h3))};
        __nv_bfloat16* rp = d + (size_t)m*3*R + col;
        reinterpret_cast<__nv_bfloat162*>(rp)[0]         = ha;
        reinterpret_cast<__nv_bfloat162*>(rp)[1]         = hb;
        reinterpret_cast<__nv_bfloat162*>(rp + R)[0]     = ha;
        reinterpret_cast<__nv_bfloat162*>(rp + R)[1]     = hb;
        reinterpret_cast<__nv_bfloat162*>(rp + 2*R)[0]   = la;
        reinterpret_cast<__nv_bfloat162*>(rp + 2*R)[1]   = lb;
    }
}

// ---------------- prep ----------------
__global__ void prep_kernel(const float* __restrict__ u_x, const float* __restrict__ w_x,
                            const float* __restrict__ dia_x,
                            const float* __restrict__ u_h, const float* __restrict__ w_h,
                            const float* __restrict__ dia_h, const float* __restrict__ h0)
{
    int n = blockIdx.x*blockDim.x + threadIdx.x;   // 0..8191
    const float *u, *w, *dia; float* o; int idx;
    if (n < G4H) { u=u_x; w=w_x; dia=dia_x; o=g_d2x; idx=n; }
    else         { u=u_h; w=w_h; dia=dia_h; o=g_d2h; idx=n-G4H; }
    int d = idx & (H-1);
    const float4* ur = reinterpret_cast<const float4*>(u + (size_t)d*R);
    const float4* wr = reinterpret_cast<const float4*>(w + (size_t)idx*R);
    float s = 0.f;
    #pragma unroll 8
    for (int k = 0; k < R/4; ++k) {
        float4 a = ur[k], b = wr[k];
        s += a.x*b.x + a.y*b.y + a.z*b.z + a.w*b.w;
    }
    o[idx] = dia[d] - s;
    for (int i = n; i < Bsz*H; i += 8192) g_h[i] = h0[i];
}

// ---------------------------------------------------------------------------
// HMMA GEMM: C[M,N] = A'[M,K'] @ B'[N,K']^T  (bf16 in, fp32 out)
//   BM=BN=128, BK=64, 256 threads (8 warps as 2x4, warp tile 64x32)
//   EPI=1: C -> P' [TB,768] bf16 hi/lo/hi;  EPI=2: Cf = C + X*d2 + bias
// ---------------------------------------------------------------------------
constexpr size_t GSM = 2*32768 + 1024;

template<int EPI>
__global__ void __launch_bounds__(256, 1) gemm_mma(
    const __nv_bfloat16* __restrict__ Ap, const __nv_bfloat16* __restrict__ Bp,
    int K, int Nld, float* __restrict__ Cf, __nv_bfloat16* __restrict__ Pp,
    const float* __restrict__ X, const float* __restrict__ d2v,
    const float* __restrict__ bias)
{
    extern __shared__ char smraw[];
    const uint32_t sb = (smem_u32(smraw) + 1023) & ~1023u;
    const int tid = threadIdx.x, lane = tid & 31, wid = tid >> 5;
    const int wm = wid >> 2, wn = wid & 3;                  // 2 x 4 warp grid
    const int m0 = blockIdx.y * 128, n0 = blockIdx.x * 128;

    const __nv_bfloat16* Asrc = Ap + (size_t)m0 * K;
    const __nv_bfloat16* Bsrc = Bp + (size_t)n0 * K;
    const int lrow = tid >> 3, lc8 = tid & 7;

    auto load_stage = [&](int kc, int s) {
        uint32_t base = sb + s * 32768;
        #pragma unroll
        for (int rr = 0; rr < 4; ++rr) {
            int row = lrow + rr * 32;
            cp16(base + swz(row*128 + lc8*16),
                 Asrc + (size_t)row*K + kc + lc8*8);
            cp16(base + 16384 + swz(row*128 + lc8*16),
                 Bsrc + (size_t)row*K + kc + lc8*8);
        }
        asm volatile("cp.async.commit_group;" ::: "memory");
    };

    float acc[4][4][4];
    #pragma unroll
    for (int a = 0; a < 4; ++a)
        #pragma unroll
        for (int b = 0; b < 4; ++b)
            #pragma unroll
            for (int c = 0; c < 4; ++c) acc[a][b][c] = 0.f;

    const int nIter = K / 64;
    load_stage(0, 0);
    for (int it = 0; it < nIter; ++it) {
        if (it + 1 < nIter) {
            load_stage((it + 1) * 64, (it + 1) & 1);
            asm volatile("cp.async.wait_group 1;" ::: "memory");
        } else {
            asm volatile("cp.async.wait_group 0;" ::: "memory");
        }
        __syncthreads();
        const uint32_t aB = sb + (it & 1) * 32768;
        const uint32_t bB = aB + 16384;
        #pragma unroll
        for (int kk = 0; kk < 4; ++kk) {
            uint32_t afr[4][4];
            #pragma unroll
            for (int mi = 0; mi < 4; ++mi) {
                int rowa = wm*64 + mi*16 + (lane & 15);
                ldsm4(afr[mi], aB + swz(rowa*128 + kk*32 + (lane >> 4)*16));
            }
            uint32_t bfr[2][4];
            #pragma unroll
            for (int nb = 0; nb < 2; ++nb) {
                int sub = lane >> 3;
                int rn = wn*32 + nb*16 + (sub >> 1)*8 + (lane & 7);
                ldsm4(bfr[nb], bB + swz(rn*128 + kk*32 + (sub & 1)*16));
            }
            #pragma unroll
            for (int mi = 0; mi < 4; ++mi)
                #pragma unroll
                for (int nb = 0; nb < 2; ++nb) {
                    mma16816(acc[mi][nb*2],     afr[mi], bfr[nb][0], bfr[nb][1]);
                    mma16816(acc[mi][nb*2 + 1], afr[mi], bfr[nb][2], bfr[nb][3]);
                }
        }
        __syncthreads();
    }

    // epilogue
    const int quad = lane >> 2, tx2 = (lane & 3) * 2;
    #pragma unroll
    for (int mi = 0; mi < 4; ++mi) {
        #pragma unroll
        for (int n8 = 0; n8 < 4; ++n8) {
            int n = n0 + wn*32 + n8*8 + tx2;
            #pragma unroll
            for (int half = 0; half < 2; ++half) {
                int m = m0 + wm*64 + mi*16 + quad + half*8;
                float v0 = acc[mi][n8][half*2], v1 = acc[mi][n8][half*2 + 1];
                if constexpr (EPI == 2) {
                    float x0 = X[(size_t)m*H + (n & (H-1))];
                    float x1 = X[(size_t)m*H + ((n+1) & (H-1))];
                    v0 += x0*d2v[n]   + bias[n];
                    v1 += x1*d2v[n+1] + bias[n+1];
                    *reinterpret_cast<float2*>(&Cf[(size_t)m*Nld + n]) =
                        make_float2(v0, v1);
                } else {
                    __nv_bfloat16 h0 = __float2bfloat16(v0);
                    __nv_bfloat16 h1 = __float2bfloat16(v1);
                    __nv_bfloat162 hh{h0, h1};
                    __nv_bfloat162 ll{__float2bfloat16(v0 - __bfloat162float(h0)),
                                      __float2bfloat16(v1 - __bfloat162float(h1))};
                    __nv_bfloat16* rp = Pp + (size_t)m*(3*R) + n;
                    *reinterpret_cast<__nv_bfloat162*>(rp)         = hh;
                    *reinterpret_cast<__nv_bfloat162*>(rp + R)     = ll;
                    *reinterpret_cast<__nv_bfloat162*>(rp + 2*R)   = hh;
                }
            }
        }
    }
}

// ---------------------------------------------------------------------------
// persistent recurrent kernel (unchanged passing version)
// ---------------------------------------------------------------------------
constexpr int SU_ST=1028, SU_F=16*SU_ST, SW_ST=260, SW_F=32*SW_ST, RED_F=512;
constexpr int SB_F=64*260, SMEM_F=SU_F+SW_F+RED_F+SB_F;
constexpr size_t SMEM_BYTES=(size_t)SMEM_F*4;

__global__ void __launch_bounds__(NTH, 1) lstm_rec(
    const float* __restrict__ c0, const float* __restrict__ h0,
    const float* __restrict__ u_h, const float* __restrict__ w_h,
    const float* __restrict__ b_h, float* __restrict__ out, int full_out)
{
    extern __shared__ float sm[];
    float* su = sm;
    float* swt = sm + SU_F;
    float* red = swt + SW_F;
    float* sbuf = red + RED_F;

    const int tid = threadIdx.x, bk = blockIdx.x;
    const int rb = bk & 15, bb = bk >> 4;
    const int r_l = tid & 15, b_l = (tid >> 4) & 7, q = tid >> 7;
    const int jl2 = tid & 7, b2 = tid >> 3;
    const int j = bk * 8 + jl2;

    for (int i = tid; i < 16*1024; i += NTH) {
        int rl = i >> 10, d = i & 1023;
        su[rl*SU_ST + d] = u_h[(size_t)d*R + rb*16 + rl];
    }
    for (int i = tid; i < 32*256; i += NTH) {
        int row = i >> 8, r = i & 255;
        int g = row >> 3, jj = row & 7;
        swt[row*SW_ST + r] = w_h[(size_t)(g*H + bk*8 + jj)*R + r];
    }
    float d2r[4], bhr[4];
    #pragma unroll
    for (int g = 0; g < 4; ++g) { d2r[g] = g_d2h[g*H + j]; bhr[g] = b_h[g*H + j]; }
    float hr = h0[b2*H + j];
    float cr = c0[b2*H + j];
    __syncthreads();

    for (int t = 0; t < T; ++t) {
        for (int i = tid; i < 8*256; i += NTH) {
            int row = i >> 8, c = i & 255;
            *reinterpret_cast<float4*>(&sbuf[row*SU_ST + c*4]) =
                __ldcg(reinterpret_cast<const float4*>(&g_h[(bb*8 + row)*H + c*4]));
        }
        __syncthreads();
        {
            unsigned long long a0 = 0ull, a1 = 0ull;
            const ulonglong2* hp = reinterpret_cast<const ulonglong2*>(&sbuf[b_l*SU_ST + q*256]);
            const ulonglong2* up = reinterpret_cast<const ulonglong2*>(&su[r_l*SU_ST + q*256]);
            #pragma unroll 8
            for (int k = 0; k < 64; ++k) {
                ulonglong2 hh = hp[k], uu = up[k];
                fma2(a0, hh.x, uu.x);
                fma2(a1, hh.y, uu.y);
            }
            float2 f0 = unpack2(a0), f1 = unpack2(a1);
            red[tid] = (f0.x + f0.y) + (f1.x + f1.y);
        }
        __syncthreads();
        if (tid < 128) {
            float s = red[tid] + red[tid+128] + red[tid+256] + red[tid+384];
            int b = bb*8 + (tid >> 4), r = rb*16 + (tid & 15);
            __stcg(&g_p[b*R + r], s);
        }
        gbar();

        const float* gp = g_Gx + (size_t)t*(Bsz*G4H) + (size_t)b2*G4H + j;
        float gx0 = __ldcs(gp);
        float gx1 = __ldcs(gp + H);
        float gx2 = __ldcs(gp + 2*H);
        float gx3 = __ldcs(gp + 3*H);

        for (int i = tid; i < 64*64; i += NTH) {
            int bbx = i >> 6, c = i & 63;
            *reinterpret_cast<float4*>(&sbuf[bbx*260 + c*4]) =
                __ldcg(reinterpret_cast<const float4*>(g_p) + i);
        }
        __syncthreads();

        unsigned long long A0=0,A1=0,B0=0,B1=0,C0=0,C1=0,D0=0,D1=0;
        {
            const ulonglong2* pp = reinterpret_cast<const ulonglong2*>(&sbuf[b2*260]);
            const ulonglong2* w0 = reinterpret_cast<const ulonglong2*>(&swt[(0*8+jl2)*SW_ST]);
            const ulonglong2* w1 = reinterpret_cast<const ulonglong2*>(&swt[(1*8+jl2)*SW_ST]);
            const ulonglong2* w2 = reinterpret_cast<const ulonglong2*>(&swt[(2*8+jl2)*SW_ST]);
            const ulonglong2* w3 = reinterpret_cast<const ulonglong2*>(&swt[(3*8+jl2)*SW_ST]);
            #pragma unroll 8
            for (int k = 0; k < 64; ++k) {
                ulonglong2 pv = pp[k];
                ulonglong2 w;
                w = w0[k]; fma2(A0, pv.x, w.x); fma2(A1, pv.y, w.y);
                w = w1[k]; fma2(B0, pv.x, w.x); fma2(B1, pv.y, w.y);
                w = w2[k]; fma2(C0, pv.x, w.x); fma2(C1, pv.y, w.y);
                w = w3[k]; fma2(D0, pv.x, w.x); fma2(D1, pv.y, w.y);
            }
        }
        float2 fa0=unpack2(A0), fa1=unpack2(A1), fb0=unpack2(B0), fb1=unpack2(B1);
        float2 fc0=unpack2(C0), fc1=unpack2(C1), fd0=unpack2(D0), fd1=unpack2(D1);
        float pi = (fa0.x+fa0.y)+(fa1.x+fa1.y) + hr*d2r[0] + bhr[0] + gx0;
        float pf = (fb0.x+fb0.y)+(fb1.x+fb1.y) + hr*d2r[1] + bhr[1] + gx1;
        float po = (fc0.x+fc0.y)+(fc1.x+fc1.y) + hr*d2r[2] + bhr[2] + gx2;
        float pn = (fd0.x+fd0.y)+(fd1.x+fd1.y) + hr*d2r[3] + bhr[3] + gx3;

        float ig = 1.f/(1.f+expf(-pi));
        float fg = 1.f/(1.f+expf(-pf));
        float og = 1.f/(1.f+expf(-po));
        float ng = tanhf(pn);
        cr = fg*cr + ig*ng;
        hr = og*tanhf(cr);

        __stcg(&g_h[b2*H + j], hr);
        __stcs(&out[(size_t)t*(Bsz*H) + b2*H + j], hr);
        if (t == T-1 && full_out) {
            out[(size_t)T*Bsz*H + b2*H + j]          = hr;
            out[(size_t)T*Bsz*H + Bsz*H + b2*H + j]  = cr;
        }
        gbar();
    }
}

// ---------------------------------------------------------------------------
extern "C" void kernel_launch(void* const* d_in, const int* in_sizes, int n_in,
                              void* d_out, int out_size)
{
    const float* x     = (const float*)d_in[0];
    const float* h0    = (const float*)d_in[1];
    const float* c0    = (const float*)d_in[2];
    const float* u_x   = (const float*)d_in[3];
    const float* u_h   = (const float*)d_in[4];
    const float* w_x   = (const float*)d_in[5];
    const float* w_h   = (const float*)d_in[6];
    const float* b_x   = (const float*)d_in[7];
    const float* b_h   = (const float*)d_in[8];
    const float* dia_x = (const float*)d_in[9];
    const float* dia_h = (const float*)d_in[10];
    float* out = (float*)d_out;

    float *pGx=nullptr, *pd2x=nullptr;
    __nv_bfloat16 *pXp=nullptr, *pWp=nullptr, *pUp=nullptr, *pPp=nullptr;
    cudaGetSymbolAddress((void**)&pGx,  g_Gx);
    cudaGetSymbolAddress((void**)&pd2x, g_d2x);
    cudaGetSymbolAddress((void**)&pXp,  g_Xp);
    cudaGetSymbolAddress((void**)&pWp,  g_Wp);
    cudaGetSymbolAddress((void**)&pUp,  g_Up);
    cudaGetSymbolAddress((void**)&pPp,  g_Pp);

    prep_kernel<<<32, 256>>>(u_x, w_x, dia_x, u_h, w_h, dia_h, h0);
    conv_pack<<<2048, 256>>>(x, pXp, 10, TB*D/4);     // X'  [TB, 3072]
    conv_wB  <<<512,  256>>>(w_x, pWp);               // Wx' [4096, 768]
    conv_uT  <<<256,  256>>>(u_x, pUp);               // UxT'[256, 3072]

    cudaFuncSetAttribute(gemm_mma<1>, cudaFuncAttributeMaxDynamicSharedMemorySize, (int)GSM);
    cudaFuncSetAttribute(gemm_mma<2>, cudaFuncAttributeMaxDynamicSharedMemorySize, (int)GSM);

    // P' = X' @ UxT'^T  (M=16384, N=256, K'=3072) -> bf16 hi/lo/hi packed
    {
        dim3 grid(R/128, TB/128);
        gemm_mma<1><<<grid, 256, GSM>>>(pXp, pUp, 3*D, 0,
                                        nullptr, pPp, nullptr, nullptr, nullptr);
    }
    // Gx = P' @ Wx'^T + x*d2_x + b_x   (M=16384, N=4096, K'=768) -> fp32
    {
        dim3 grid(G4H/128, TB/128);
        gemm_mma<2><<<grid, 256, GSM>>>(pPp, pWp, 3*R, G4H,
                                        pGx, nullptr, x, pd2x, b_x);
    }
    cudaFuncSetAttribute(lstm_rec, cudaFuncAttributeMaxDynamicSharedMemorySize, (int)SMEM_BYTES);
    int full_out = (out_size >= T*Bsz*H + 2*Bsz*H) ? 1 : 0;
    lstm_rec<<<NB, NTH, SMEM_BYTES>>>(c0, h0, u_h, w_h, b_h, out, full_out);
}

// round 10
// speedup vs baseline: 1.2302x; 1.1160x over previous
#include <cuda_runtime.h>
#include <cuda_bf16.h>
#include <cstdint>
#include <cstddef>

constexpr int T=256, Bsz=64, D=1024, H=1024, R=256;
constexpr int G4H=4*H, TB=T*Bsz, NB=128, NTH=512;

// static scratch (allocation-free)
// packed 3-pass layouts: A' = [hi | lo | hi], B' = [hi | hi | lo] along K
__device__ __align__(256) __nv_bfloat16 g_Xp[(size_t)TB*3*D];    // X'  [TB, 3072]
__device__ __align__(256) __nv_bfloat16 g_Wp[(size_t)G4H*3*R];   // Wx' [4096, 768]
__device__ __align__(256) __nv_bfloat16 g_Up[(size_t)R*3*D];     // UxT'[256, 3072]
__device__ __align__(256) __nv_bfloat16 g_Pp[(size_t)TB*3*R];    // P'  [TB, 768]
__device__ float g_Gx[(size_t)TB*G4H];
__device__ float g_d2x[G4H];
__device__ float g_d2h[G4H];
__device__ float g_h[Bsz*H];
__device__ float g_p[Bsz*R];
__device__ unsigned g_count;

// ---------------- helpers ----------------
__device__ __forceinline__ void fma2(unsigned long long& acc,
                                     unsigned long long a, unsigned long long b) {
    asm("fma.rn.f32x2 %0, %1, %2, %0;" : "+l"(acc) : "l"(a), "l"(b));
}
__device__ __forceinline__ float2 unpack2(unsigned long long v) {
    float2 f; asm("mov.b64 {%0, %1}, %2;" : "=f"(f.x), "=f"(f.y) : "l"(v)); return f;
}
__device__ __forceinline__ uint32_t smem_u32(const void* p) {
    uint32_t a;
    asm("{ .reg .u64 t; cvta.to.shared.u64 t, %1; cvt.u32.u64 %0, t; }" : "=r"(a) : "l"(p));
    return a;
}
__device__ __forceinline__ void cp16(uint32_t dst, const void* src) {
    asm volatile("cp.async.cg.shared.global [%0], [%1], 16;" :: "r"(dst), "l"(src) : "memory");
}
__device__ __forceinline__ uint32_t swz(uint32_t o) { return o ^ ((o >> 3) & 0x70); }

__device__ __forceinline__ void ldsm4(uint32_t* r, uint32_t addr) {
    asm volatile("ldmatrix.sync.aligned.m8n8.x4.shared.b16 {%0,%1,%2,%3}, [%4];"
        : "=r"(r[0]), "=r"(r[1]), "=r"(r[2]), "=r"(r[3]) : "r"(addr));
}
__device__ __forceinline__ void mma16816(float* c, const uint32_t* a,
                                         uint32_t b0, uint32_t b1) {
    asm volatile(
        "mma.sync.aligned.m16n8k16.row.col.f32.bf16.bf16.f32 "
        "{%0,%1,%2,%3}, {%4,%5,%6,%7}, {%8,%9}, {%0,%1,%2,%3};"
        : "+f"(c[0]), "+f"(c[1]), "+f"(c[2]), "+f"(c[3])
        : "r"(a[0]), "r"(a[1]), "r"(a[2]), "r"(a[3]), "r"(b0), "r"(b1));
}

// ---------------- grid barrier: release/acquire flag, NO per-thread membar ----
// Monotonic counter; barrier k complete when g_count >= k*NB.
// bar.sync gives intra-CTA HB; red.release / ld.acquire gives inter-CTA HB;
// transitivity through tid0 makes all pre-barrier stores visible post-barrier.
__device__ __forceinline__ void gbar(unsigned target) {
    __syncthreads();
    if (threadIdx.x == 0) {
        asm volatile("red.release.gpu.global.add.u32 [%0], 1;"
                     :: "l"(&g_count) : "memory");
        unsigned v;
        do {
            asm volatile("ld.acquire.gpu.global.u32 %0, [%1];"
                         : "=r"(v) : "l"(&g_count) : "memory");
        } while (v < target);
    }
    __syncthreads();
}

// ---------------- conversions ----------------
__global__ void conv_pack(const float* __restrict__ s, __nv_bfloat16* __restrict__ d,
                          int ls, int n4)
{
    const int rl = 1 << ls, mask = rl - 1;
    for (int i = blockIdx.x*blockDim.x + threadIdx.x; i < n4; i += gridDim.x*blockDim.x) {
        float4 v = reinterpret_cast<const float4*>(s)[i];
        int e = i * 4, m = e >> ls, col = e & mask;
        __nv_bfloat16 h0=__float2bfloat16(v.x), h1=__float2bfloat16(v.y);
        __nv_bfloat16 h2=__float2bfloat16(v.z), h3=__float2bfloat16(v.w);
        __nv_bfloat162 ha{h0,h1}, hb{h2,h3};
        __nv_bfloat162 la{__float2bfloat16(v.x-__bfloat162float(h0)),
                          __float2bfloat16(v.y-__bfloat162float(h1))};
        __nv_bfloat162 lb{__float2bfloat16(v.z-__bfloat162float(h2)),
                          __float2bfloat16(v.w-__bfloat162float(h3))};
        __nv_bfloat16* rp = d + (size_t)m*3*rl + col;
        reinterpret_cast<__nv_bfloat162*>(rp)[0]        = ha;
        reinterpret_cast<__nv_bfloat162*>(rp)[1]        = hb;
        reinterpret_cast<__nv_bfloat162*>(rp + rl)[0]   = la;
        reinterpret_cast<__nv_bfloat162*>(rp + rl)[1]   = lb;
        reinterpret_cast<__nv_bfloat162*>(rp + 2*rl)[0] = ha;
        reinterpret_cast<__nv_bfloat162*>(rp + 2*rl)[1] = hb;
    }
}
__global__ void conv_uT(const float* __restrict__ u, __nv_bfloat16* __restrict__ d)
{
    for (int i = blockIdx.x*blockDim.x + threadIdx.x; i < R*D; i += gridDim.x*blockDim.x) {
        int n = i >> 10, dd = i & 1023;
        float v = u[(size_t)dd*R + n];
        __nv_bfloat16 h = __float2bfloat16(v);
        __nv_bfloat16 l = __float2bfloat16(v - __bfloat162float(h));
        d[(size_t)n*3*D + dd]       = h;
        d[(size_t)n*3*D + D + dd]   = h;
        d[(size_t)n*3*D + 2*D + dd] = l;
    }
}
__global__ void conv_wB(const float* __restrict__ w, __nv_bfloat16* __restrict__ d)
{
    for (int i = blockIdx.x*blockDim.x + threadIdx.x; i < G4H*R/4; i += gridDim.x*blockDim.x) {
        float4 v = reinterpret_cast<const float4*>(w)[i];
        int e = i * 4, m = e >> 8, col = e & 255;
        __nv_bfloat16 h0=__float2bfloat16(v.x), h1=__float2bfloat16(v.y);
        __nv_bfloat16 h2=__float2bfloat16(v.z), h3=__float2bfloat16(v.w);
        __nv_bfloat162 ha{h0,h1}, hb{h2,h3};
        __nv_bfloat162 la{__float2bfloat16(v.x-__bfloat162float(h0)),
                          __float2bfloat16(v.y-__bfloat162float(h1))};
        __nv_bfloat162 lb{__float2bfloat16(v.z-__bfloat162float(h2)),
                          __float2bfloat16(v.w-__bfloat162float(h3))};
        __nv_bfloat16* rp = d + (size_t)m*3*R + col;
        reinterpret_cast<__nv_bfloat162*>(rp)[0]         = ha;
        reinterpret_cast<__nv_bfloat162*>(rp)[1]         = hb;
        reinterpret_cast<__nv_bfloat162*>(rp + R)[0]     = ha;
        reinterpret_cast<__nv_bfloat162*>(rp + R)[1]     = hb;
        reinterpret_cast<__nv_bfloat162*>(rp + 2*R)[0]   = la;
        reinterpret_cast<__nv_bfloat162*>(rp + 2*R)[1]   = lb;
    }
}

// ---------------- prep ----------------
__global__ void prep_kernel(const float* __restrict__ u_x, const float* __restrict__ w_x,
                            const float* __restrict__ dia_x,
                            const float* __restrict__ u_h, const float* __restrict__ w_h,
                            const float* __restrict__ dia_h, const float* __restrict__ h0)
{
    int n = blockIdx.x*blockDim.x + threadIdx.x;   // 0..8191
    if (n == 0) g_count = 0u;                      // reset barrier counter (graph-replay safe)
    const float *u, *w, *dia; float* o; int idx;
    if (n < G4H) { u=u_x; w=w_x; dia=dia_x; o=g_d2x; idx=n; }
    else         { u=u_h; w=w_h; dia=dia_h; o=g_d2h; idx=n-G4H; }
    int d = idx & (H-1);
    const float4* ur = reinterpret_cast<const float4*>(u + (size_t)d*R);
    const float4* wr = reinterpret_cast<const float4*>(w + (size_t)idx*R);
    float s = 0.f;
    #pragma unroll 8
    for (int k = 0; k < R/4; ++k) {
        float4 a = ur[k], b = wr[k];
        s += a.x*b.x + a.y*b.y + a.z*b.z + a.w*b.w;
    }
    o[idx] = dia[d] - s;
    for (int i = n; i < Bsz*H; i += 8192) g_h[i] = h0[i];
}

// ---------------------------------------------------------------------------
// HMMA GEMM (unchanged from R9)
// ---------------------------------------------------------------------------
constexpr size_t GSM = 2*32768 + 1024;

template<int EPI>
__global__ void __launch_bounds__(256, 1) gemm_mma(
    const __nv_bfloat16* __restrict__ Ap, const __nv_bfloat16* __restrict__ Bp,
    int K, int Nld, float* __restrict__ Cf, __nv_bfloat16* __restrict__ Pp,
    const float* __restrict__ X, const float* __restrict__ d2v,
    const float* __restrict__ bias)
{
    extern __shared__ char smraw[];
    const uint32_t sb = (smem_u32(smraw) + 1023) & ~1023u;
    const int tid = threadIdx.x, lane = tid & 31, wid = tid >> 5;
    const int wm = wid >> 2, wn = wid & 3;
    const int m0 = blockIdx.y * 128, n0 = blockIdx.x * 128;

    const __nv_bfloat16* Asrc = Ap + (size_t)m0 * K;
    const __nv_bfloat16* Bsrc = Bp + (size_t)n0 * K;
    const int lrow = tid >> 3, lc8 = tid & 7;

    auto load_stage = [&](int kc, int s) {
        uint32_t base = sb + s * 32768;
        #pragma unroll
        for (int rr = 0; rr < 4; ++rr) {
            int row = lrow + rr * 32;
            cp16(base + swz(row*128 + lc8*16),
                 Asrc + (size_t)row*K + kc + lc8*8);
            cp16(base + 16384 + swz(row*128 + lc8*16),
                 Bsrc + (size_t)row*K + kc + lc8*8);
        }
        asm volatile("cp.async.commit_group;" ::: "memory");
    };

    float acc[4][4][4];
    #pragma unroll
    for (int a = 0; a < 4; ++a)
        #pragma unroll
        for (int b = 0; b < 4; ++b)
            #pragma unroll
            for (int c = 0; c < 4; ++c) acc[a][b][c] = 0.f;

    const int nIter = K / 64;
    load_stage(0, 0);
    for (int it = 0; it < nIter; ++it) {
        if (it + 1 < nIter) {
            load_stage((it + 1) * 64, (it + 1) & 1);
            asm volatile("cp.async.wait_group 1;" ::: "memory");
        } else {
            asm volatile("cp.async.wait_group 0;" ::: "memory");
        }
        __syncthreads();
        const uint32_t aB = sb + (it & 1) * 32768;
        const uint32_t bB = aB + 16384;
        #pragma unroll
        for (int kk = 0; kk < 4; ++kk) {
            uint32_t afr[4][4];
            #pragma unroll
            for (int mi = 0; mi < 4; ++mi) {
                int rowa = wm*64 + mi*16 + (lane & 15);
                ldsm4(afr[mi], aB + swz(rowa*128 + kk*32 + (lane >> 4)*16));
            }
            uint32_t bfr[2][4];
            #pragma unroll
            for (int nb = 0; nb < 2; ++nb) {
                int sub = lane >> 3;
                int rn = wn*32 + nb*16 + (sub >> 1)*8 + (lane & 7);
                ldsm4(bfr[nb], bB + swz(rn*128 + kk*32 + (sub & 1)*16));
            }
            #pragma unroll
            for (int mi = 0; mi < 4; ++mi)
                #pragma unroll
                for (int nb = 0; nb < 2; ++nb) {
                    mma16816(acc[mi][nb*2],     afr[mi], bfr[nb][0], bfr[nb][1]);
                    mma16816(acc[mi][nb*2 + 1], afr[mi], bfr[nb][2], bfr[nb][3]);
                }
        }
        __syncthreads();
    }

    const int quad = lane >> 2, tx2 = (lane & 3) * 2;
    #pragma unroll
    for (int mi = 0; mi < 4; ++mi) {
        #pragma unroll
        for (int n8 = 0; n8 < 4; ++n8) {
            int n = n0 + wn*32 + n8*8 + tx2;
            #pragma unroll
            for (int half = 0; half < 2; ++half) {
                int m = m0 + wm*64 + mi*16 + quad + half*8;
                float v0 = acc[mi][n8][half*2], v1 = acc[mi][n8][half*2 + 1];
                if constexpr (EPI == 2) {
                    float x0 = X[(size_t)m*H + (n & (H-1))];
                    float x1 = X[(size_t)m*H + ((n+1) & (H-1))];
                    v0 += x0*d2v[n]   + bias[n];
                    v1 += x1*d2v[n+1] + bias[n+1];
                    *reinterpret_cast<float2*>(&Cf[(size_t)m*Nld + n]) =
                        make_float2(v0, v1);
                } else {
                    __nv_bfloat16 h0 = __float2bfloat16(v0);
                    __nv_bfloat16 h1 = __float2bfloat16(v1);
                    __nv_bfloat162 hh{h0, h1};
                    __nv_bfloat162 ll{__float2bfloat16(v0 - __bfloat162float(h0)),
                                      __float2bfloat16(v1 - __bfloat162float(h1))};
                    __nv_bfloat16* rp = Pp + (size_t)m*(3*R) + n;
                    *reinterpret_cast<__nv_bfloat162*>(rp)         = hh;
                    *reinterpret_cast<__nv_bfloat162*>(rp + R)     = ll;
                    *reinterpret_cast<__nv_bfloat162*>(rp + 2*R)   = hh;
                }
            }
        }
    }
}

// ---------------------------------------------------------------------------
// persistent recurrent kernel — same structure, new barrier protocol
// ---------------------------------------------------------------------------
constexpr int SU_ST=1028, SU_F=16*SU_ST, SW_ST=260, SW_F=32*SW_ST, RED_F=512;
constexpr int SB_F=64*260, SMEM_F=SU_F+SW_F+RED_F+SB_F;
constexpr size_t SMEM_BYTES=(size_t)SMEM_F*4;

__global__ void __launch_bounds__(NTH, 1) lstm_rec(
    const float* __restrict__ c0, const float* __restrict__ h0,
    const float* __restrict__ u_h, const float* __restrict__ w_h,
    const float* __restrict__ b_h, float* __restrict__ out, int full_out)
{
    extern __shared__ float sm[];
    float* su = sm;
    float* swt = sm + SU_F;
    float* red = swt + SW_F;
    float* sbuf = red + RED_F;

    const int tid = threadIdx.x, bk = blockIdx.x;
    const int rb = bk & 15, bb = bk >> 4;
    const int r_l = tid & 15, b_l = (tid >> 4) & 7, q = tid >> 7;
    const int jl2 = tid & 7, b2 = tid >> 3;
    const int j = bk * 8 + jl2;

    for (int i = tid; i < 16*1024; i += NTH) {
        int rl = i >> 10, d = i & 1023;
        su[rl*SU_ST + d] = u_h[(size_t)d*R + rb*16 + rl];
    }
    for (int i = tid; i < 32*256; i += NTH) {
        int row = i >> 8, r = i & 255;
        int g = row >> 3, jj = row & 7;
        swt[row*SW_ST + r] = w_h[(size_t)(g*H + bk*8 + jj)*R + r];
    }
    float d2r[4], bhr[4];
    #pragma unroll
    for (int g = 0; g < 4; ++g) { d2r[g] = g_d2h[g*H + j]; bhr[g] = b_h[g*H + j]; }
    float hr = h0[b2*H + j];
    float cr = c0[b2*H + j];
    __syncthreads();

    unsigned bar = 0;
    for (int t = 0; t < T; ++t) {
        // ---- phase 1: p[8b,16r] = h[8b,:] @ u_h[:,16r] ----
        for (int i = tid; i < 8*256; i += NTH) {
            int row = i >> 8, c = i & 255;
            *reinterpret_cast<float4*>(&sbuf[row*SU_ST + c*4]) =
                __ldcg(reinterpret_cast<const float4*>(&g_h[(bb*8 + row)*H + c*4]));
        }
        __syncthreads();
        {
            unsigned long long a0 = 0ull, a1 = 0ull;
            const ulonglong2* hp = reinterpret_cast<const ulonglong2*>(&sbuf[b_l*SU_ST + q*256]);
            const ulonglong2* up = reinterpret_cast<const ulonglong2*>(&su[r_l*SU_ST + q*256]);
            #pragma unroll 8
            for (int k = 0; k < 64; ++k) {
                ulonglong2 hh = hp[k], uu = up[k];
                fma2(a0, hh.x, uu.x);
                fma2(a1, hh.y, uu.y);
            }
            float2 f0 = unpack2(a0), f1 = unpack2(a1);
            red[tid] = (f0.x + f0.y) + (f1.x + f1.y);
        }
        __syncthreads();
        if (tid < 128) {
            float s = red[tid] + red[tid+128] + red[tid+256] + red[tid+384];
            int b = bb*8 + (tid >> 4), r = rb*16 + (tid & 15);
            __stcg(&g_p[b*R + r], s);
        }
        bar += NB; gbar(bar);

        // ---- phase 2: gates + state update ----
        const float* gp = g_Gx + (size_t)t*(Bsz*G4H) + (size_t)b2*G4H + j;
        float gx0 = __ldcs(gp);
        float gx1 = __ldcs(gp + H);
        float gx2 = __ldcs(gp + 2*H);
        float gx3 = __ldcs(gp + 3*H);

        for (int i = tid; i < 64*64; i += NTH) {
            int bbx = i >> 6, c = i & 63;
            *reinterpret_cast<float4*>(&sbuf[bbx*260 + c*4]) =
                __ldcg(reinterpret_cast<const float4*>(g_p) + i);
        }
        __syncthreads();

        unsigned long long A0=0,A1=0,B0=0,B1=0,C0=0,C1=0,D0=0,D1=0;
        {
            const ulonglong2* pp = reinterpret_cast<const ulonglong2*>(&sbuf[b2*260]);
            const ulonglong2* w0 = reinterpret_cast<const ulonglong2*>(&swt[(0*8+jl2)*SW_ST]);
            const ulonglong2* w1 = reinterpret_cast<const ulonglong2*>(&swt[(1*8+jl2)*SW_ST]);
            const ulonglong2* w2 = reinterpret_cast<const ulonglong2*>(&swt[(2*8+jl2)*SW_ST]);
            const ulonglong2* w3 = reinterpret_cast<const ulonglong2*>(&swt[(3*8+jl2)*SW_ST]);
            #pragma unroll 8
            for (int k = 0; k < 64; ++k) {
                ulonglong2 pv = pp[k];
                ulonglong2 w;
                w = w0[k]; fma2(A0, pv.x, w.x); fma2(A1, pv.y, w.y);
                w = w1[k]; fma2(B0, pv.x, w.x); fma2(B1, pv.y, w.y);
                w = w2[k]; fma2(C0, pv.x, w.x); fma2(C1, pv.y, w.y);
                w = w3[k]; fma2(D0, pv.x, w.x); fma2(D1, pv.y, w.y);
            }
        }
        float2 fa0=unpack2(A0), fa1=unpack2(A1), fb0=unpack2(B0), fb1=unpack2(B1);
        float2 fc0=unpack2(C0), fc1=unpack2(C1), fd0=unpack2(D0), fd1=unpack2(D1);
        float pi = (fa0.x+fa0.y)+(fa1.x+fa1.y) + hr*d2r[0] + bhr[0] + gx0;
        float pf = (fb0.x+fb0.y)+(fb1.x+fb1.y) + hr*d2r[1] + bhr[1] + gx1;
        float po = (fc0.x+fc0.y)+(fc1.x+fc1.y) + hr*d2r[2] + bhr[2] + gx2;
        float pn = (fd0.x+fd0.y)+(fd1.x+fd1.y) + hr*d2r[3] + bhr[3] + gx3;

        float ig = 1.f/(1.f+expf(-pi));
        float fg = 1.f/(1.f+expf(-pf));
        float og = 1.f/(1.f+expf(-po));
        float ng = tanhf(pn);
        cr = fg*cr + ig*ng;
        hr = og*tanhf(cr);

        __stcg(&g_h[b2*H + j], hr);
        __stcs(&out[(size_t)t*(Bsz*H) + b2*H + j], hr);
        if (t == T-1 && full_out) {
            out[(size_t)T*Bsz*H + b2*H + j]          = hr;
            out[(size_t)T*Bsz*H + Bsz*H + b2*H + j]  = cr;
        }
        bar += NB; gbar(bar);
    }
}

// ---------------------------------------------------------------------------
extern "C" void kernel_launch(void* const* d_in, const int* in_sizes, int n_in,
                              void* d_out, int out_size)
{
    const float* x     = (const float*)d_in[0];
    const float* h0    = (const float*)d_in[1];
    const float* c0    = (const float*)d_in[2];
    const float* u_x   = (const float*)d_in[3];
    const float* u_h   = (const float*)d_in[4];
    const float* w_x   = (const float*)d_in[5];
    const float* w_h   = (const float*)d_in[6];
    const float* b_x   = (const float*)d_in[7];
    const float* b_h   = (const float*)d_in[8];
    const float* dia_x = (const float*)d_in[9];
    const float* dia_h = (const float*)d_in[10];
    float* out = (float*)d_out;

    float *pGx=nullptr, *pd2x=nullptr;
    __nv_bfloat16 *pXp=nullptr, *pWp=nullptr, *pUp=nullptr, *pPp=nullptr;
    cudaGetSymbolAddress((void**)&pGx,  g_Gx);
    cudaGetSymbolAddress((void**)&pd2x, g_d2x);
    cudaGetSymbolAddress((void**)&pXp,  g_Xp);
    cudaGetSymbolAddress((void**)&pWp,  g_Wp);
    cudaGetSymbolAddress((void**)&pUp,  g_Up);
    cudaGetSymbolAddress((void**)&pPp,  g_Pp);

    prep_kernel<<<32, 256>>>(u_x, w_x, dia_x, u_h, w_h, dia_h, h0);
    conv_pack<<<2048, 256>>>(x, pXp, 10, TB*D/4);     // X'  [TB, 3072]
    conv_wB  <<<512,  256>>>(w_x, pWp);               // Wx' [4096, 768]
    conv_uT  <<<256,  256>>>(u_x, pUp);               // UxT'[256, 3072]

    cudaFuncSetAttribute(gemm_mma<1>, cudaFuncAttributeMaxDynamicSharedMemorySize, (int)GSM);
    cudaFuncSetAttribute(gemm_mma<2>, cudaFuncAttributeMaxDynamicSharedMemorySize, (int)GSM);

    // P' = X' @ UxT'^T  (M=16384, N=256, K'=3072) -> bf16 hi/lo/hi packed
    {
        dim3 grid(R/128, TB/128);
        gemm_mma<1><<<grid, 256, GSM>>>(pXp, pUp, 3*D, 0,
                                        nullptr, pPp, nullptr, nullptr, nullptr);
    }
    // Gx = P' @ Wx'^T + x*d2_x + b_x   (M=16384, N=4096, K'=768) -> fp32
    {
        dim3 grid(G4H/128, TB/128);
        gemm_mma<2><<<grid, 256, GSM>>>(pPp, pWp, 3*R, G4H,
                                        pGx, nullptr, x, pd2x, b_x);
    }
    cudaFuncSetAttribute(lstm_rec, cudaFuncAttributeMaxDynamicSharedMemorySize, (int)SMEM_BYTES);
    int full_out = (out_size >= T*Bsz*H + 2*Bsz*H) ? 1 : 0;
    lstm_rec<<<NB, NTH, SMEM_BYTES>>>(c0, h0, u_h, w_h, b_h, out, full_out);
}

// round 12
// speedup vs baseline: 1.6620x; 1.3510x over previous
#include <cuda_runtime.h>
#include <cuda_bf16.h>
#include <cstdint>
#include <cstddef>

constexpr int T=256, Bsz=64, D=1024, H=1024, R=256;
constexpr int G4H=4*H, TB=T*Bsz, NB=128, NTH=512;

// static scratch (allocation-free)
// packed 3-pass layouts: A' = [hi | lo | hi], B' = [hi | hi | lo] along K
__device__ __align__(256) __nv_bfloat16 g_Xp[(size_t)TB*3*D];    // X'  [TB, 3072]
__device__ __align__(256) __nv_bfloat16 g_Wp[(size_t)G4H*3*R];   // Wx' [4096, 768]
__device__ __align__(256) __nv_bfloat16 g_Up[(size_t)R*3*D];     // UxT'[256, 3072]
__device__ __align__(256) __nv_bfloat16 g_Pp[(size_t)TB*3*R];    // P'  [TB, 768]
__device__ __align__(256) __nv_bfloat16 g_Whp[(size_t)G4H*3*R];  // Wh' [4096, 768]
__device__ __align__(256) __nv_bfloat16 g_pp[(size_t)Bsz*3*R];   // p'  [64, 768] per step
__device__ float g_Gx[(size_t)TB*G4H];
__device__ float g_d2x[G4H];
__device__ float g_d2h[G4H];
__device__ float g_h[Bsz*H];
__device__ unsigned g_count;

// ---------------- helpers ----------------
__device__ __forceinline__ void fma2(unsigned long long& acc,
                                     unsigned long long a, unsigned long long b) {
    asm("fma.rn.f32x2 %0, %1, %2, %0;" : "+l"(acc) : "l"(a), "l"(b));
}
__device__ __forceinline__ float2 unpack2(unsigned long long v) {
    float2 f; asm("mov.b64 {%0, %1}, %2;" : "=f"(f.x), "=f"(f.y) : "l"(v)); return f;
}
__device__ __forceinline__ uint32_t smem_u32(const void* p) {
    uint32_t a;
    asm("{ .reg .u64 t; cvta.to.shared.u64 t, %1; cvt.u32.u64 %0, t; }" : "=r"(a) : "l"(p));
    return a;
}
__device__ __forceinline__ void cp16(uint32_t dst, const void* src) {
    asm volatile("cp.async.cg.shared.global [%0], [%1], 16;" :: "r"(dst), "l"(src) : "memory");
}
__device__ __forceinline__ uint32_t swz(uint32_t o) { return o ^ ((o >> 3) & 0x70); }

__device__ __forceinline__ void ldsm4(uint32_t* r, uint32_t addr) {
    asm volatile("ldmatrix.sync.aligned.m8n8.x4.shared.b16 {%0,%1,%2,%3}, [%4];"
        : "=r"(r[0]), "=r"(r[1]), "=r"(r[2]), "=r"(r[3]) : "r"(addr));
}
__device__ __forceinline__ void mma16816(float* c, const uint32_t* a,
                                         uint32_t b0, uint32_t b1) {
    asm volatile(
        "mma.sync.aligned.m16n8k16.row.col.f32.bf16.bf16.f32 "
        "{%0,%1,%2,%3}, {%4,%5,%6,%7}, {%8,%9}, {%0,%1,%2,%3};"
        : "+f"(c[0]), "+f"(c[1]), "+f"(c[2]), "+f"(c[3])
        : "r"(a[0]), "r"(a[1]), "r"(a[2]), "r"(a[3]), "r"(b0), "r"(b1));
}

// ---------------- grid barrier (release/acquire, monotonic) ----------------
__device__ __forceinline__ void gbar(unsigned target) {
    __syncthreads();
    if (threadIdx.x == 0) {
        asm volatile("red.release.gpu.global.add.u32 [%0], 1;"
                     :: "l"(&g_count) : "memory");
        unsigned v;
        do {
            asm volatile("ld.acquire.gpu.global.u32 %0, [%1];"
                         : "=r"(v) : "l"(&g_count) : "memory");
        } while (v < target);
    }
    __syncthreads();
}

// ---------------- conversions ----------------
__global__ void conv_pack(const float* __restrict__ s, __nv_bfloat16* __restrict__ d,
                          int ls, int n4)
{
    const int rl = 1 << ls, mask = rl - 1;
    for (int i = blockIdx.x*blockDim.x + threadIdx.x; i < n4; i += gridDim.x*blockDim.x) {
        float4 v = reinterpret_cast<const float4*>(s)[i];
        int e = i * 4, m = e >> ls, col = e & mask;
        __nv_bfloat16 h0=__float2bfloat16(v.x), h1=__float2bfloat16(v.y);
        __nv_bfloat16 h2=__float2bfloat16(v.z), h3=__float2bfloat16(v.w);
        __nv_bfloat162 ha{h0,h1}, hb{h2,h3};
        __nv_bfloat162 la{__float2bfloat16(v.x-__bfloat162float(h0)),
                          __float2bfloat16(v.y-__bfloat162float(h1))};
        __nv_bfloat162 lb{__float2bfloat16(v.z-__bfloat162float(h2)),
                          __float2bfloat16(v.w-__bfloat162float(h3))};
        __nv_bfloat16* rp = d + (size_t)m*3*rl + col;
        reinterpret_cast<__nv_bfloat162*>(rp)[0]        = ha;
        reinterpret_cast<__nv_bfloat162*>(rp)[1]        = hb;
        reinterpret_cast<__nv_bfloat162*>(rp + rl)[0]   = la;
        reinterpret_cast<__nv_bfloat162*>(rp + rl)[1]   = lb;
        reinterpret_cast<__nv_bfloat162*>(rp + 2*rl)[0] = ha;
        reinterpret_cast<__nv_bfloat162*>(rp + 2*rl)[1] = hb;
    }
}
__global__ void conv_uT(const float* __restrict__ u, __nv_bfloat16* __restrict__ d)
{
    for (int i = blockIdx.x*blockDim.x + threadIdx.x; i < R*D; i += gridDim.x*blockDim.x) {
        int n = i >> 10, dd = i & 1023;
        float v = u[(size_t)dd*R + n];
        __nv_bfloat16 h = __float2bfloat16(v);
        __nv_bfloat16 l = __float2bfloat16(v - __bfloat162float(h));
        d[(size_t)n*3*D + dd]       = h;
        d[(size_t)n*3*D + D + dd]   = h;
        d[(size_t)n*3*D + 2*D + dd] = l;
    }
}
// rows of 256 fp32 -> rows of 768 bf16 [hi | hi | lo]
__global__ void conv_wB(const float* __restrict__ w, __nv_bfloat16* __restrict__ d)
{
    for (int i = blockIdx.x*blockDim.x + threadIdx.x; i < G4H*R/4; i += gridDim.x*blockDim.x) {
        float4 v = reinterpret_cast<const float4*>(w)[i];
        int e = i * 4, m = e >> 8, col = e & 255;
        __nv_bfloat16 h0=__float2bfloat16(v.x), h1=__float2bfloat16(v.y);
        __nv_bfloat16 h2=__float2bfloat16(v.z), h3=__float2bfloat16(v.w);
        __nv_bfloat162 ha{h0,h1}, hb{h2,h3};
        __nv_bfloat162 la{__float2bfloat16(v.x-__bfloat162float(h0)),
                          __float2bfloat16(v.y-__bfloat162float(h1))};
        __nv_bfloat162 lb{__float2bfloat16(v.z-__bfloat162float(h2)),
                          __float2bfloat16(v.w-__bfloat162float(h3))};
        __nv_bfloat16* rp = d + (size_t)m*3*R + col;
        reinterpret_cast<__nv_bfloat162*>(rp)[0]         = ha;
        reinterpret_cast<__nv_bfloat162*>(rp)[1]         = hb;
        reinterpret_cast<__nv_bfloat162*>(rp + R)[0]     = ha;
        reinterpret_cast<__nv_bfloat162*>(rp + R)[1]     = hb;
        reinterpret_cast<__nv_bfloat162*>(rp + 2*R)[0]   = la;
        reinterpret_cast<__nv_bfloat162*>(rp + 2*R)[1]   = lb;
    }
}

// ---------------- prep ----------------
__global__ void prep_kernel(const float* __restrict__ u_x, const float* __restrict__ w_x,
                            const float* __restrict__ dia_x,
                            const float* __restrict__ u_h, const float* __restrict__ w_h,
                            const float* __restrict__ dia_h, const float* __restrict__ h0)
{
    int n = blockIdx.x*blockDim.x + threadIdx.x;   // 0..8191
    if (n == 0) g_count = 0u;                      // barrier counter reset (replay-safe)
    const float *u, *w, *dia; float* o; int idx;
    if (n < G4H) { u=u_x; w=w_x; dia=dia_x; o=g_d2x; idx=n; }
    else         { u=u_h; w=w_h; dia=dia_h; o=g_d2h; idx=n-G4H; }
    int d = idx & (H-1);
    const float4* ur = reinterpret_cast<const float4*>(u + (size_t)d*R);
    const float4* wr = reinterpret_cast<const float4*>(w + (size_t)idx*R);
    float s = 0.f;
    #pragma unroll 8
    for (int k = 0; k < R/4; ++k) {
        float4 a = ur[k], b = wr[k];
        s += a.x*b.x + a.y*b.y + a.z*b.z + a.w*b.w;
    }
    o[idx] = dia[d] - s;
    for (int i = n; i < Bsz*H; i += 8192) g_h[i] = h0[i];
}

// ---------------------------------------------------------------------------
// HMMA GEMM for precompute (unchanged from R9/R10)
// ---------------------------------------------------------------------------
constexpr size_t GSM = 2*32768 + 1024;

template<int EPI>
__global__ void __launch_bounds__(256, 1) gemm_mma(
    const __nv_bfloat16* __restrict__ Ap, const __nv_bfloat16* __restrict__ Bp,
    int K, int Nld, float* __restrict__ Cf, __nv_bfloat16* __restrict__ Pp,
    const float* __restrict__ X, const float* __restrict__ d2v,
    const float* __restrict__ bias)
{
    extern __shared__ char smraw[];
    const uint32_t sb = (smem_u32(smraw) + 1023) & ~1023u;
    const int tid = threadIdx.x, lane = tid & 31, wid = tid >> 5;
    const int wm = wid >> 2, wn = wid & 3;
    const int m0 = blockIdx.y * 128, n0 = blockIdx.x * 128;

    const __nv_bfloat16* Asrc = Ap + (size_t)m0 * K;
    const __nv_bfloat16* Bsrc = Bp + (size_t)n0 * K;
    const int lrow = tid >> 3, lc8 = tid & 7;

    auto load_stage = [&](int kc, int s) {
        uint32_t base = sb + s * 32768;
        #pragma unroll
        for (int rr = 0; rr < 4; ++rr) {
            int row = lrow + rr * 32;
            cp16(base + swz(row*128 + lc8*16),
                 Asrc + (size_t)row*K + kc + lc8*8);
            cp16(base + 16384 + swz(row*128 + lc8*16),
                 Bsrc + (size_t)row*K + kc + lc8*8);
        }
        asm volatile("cp.async.commit_group;" ::: "memory");
    };

    float acc[4][4][4];
    #pragma unroll
    for (int a = 0; a < 4; ++a)
        #pragma unroll
        for (int b = 0; b < 4; ++b)
            #pragma unroll
            for (int c = 0; c < 4; ++c) acc[a][b][c] = 0.f;

    const int nIter = K / 64;
    load_stage(0, 0);
    for (int it = 0; it < nIter; ++it) {
        if (it + 1 < nIter) {
            load_stage((it + 1) * 64, (it + 1) & 1);
            asm volatile("cp.async.wait_group 1;" ::: "memory");
        } else {
            asm volatile("cp.async.wait_group 0;" ::: "memory");
        }
        __syncthreads();
        const uint32_t aB = sb + (it & 1) * 32768;
        const uint32_t bB = aB + 16384;
        #pragma unroll
        for (int kk = 0; kk < 4; ++kk) {
            uint32_t afr[4][4];
            #pragma unroll
            for (int mi = 0; mi < 4; ++mi) {
                int rowa = wm*64 + mi*16 + (lane & 15);
                ldsm4(afr[mi], aB + swz(rowa*128 + kk*32 + (lane >> 4)*16));
            }
            uint32_t bfr[2][4];
            #pragma unroll
            for (int nb = 0; nb < 2; ++nb) {
                int sub = lane >> 3;
                int rn = wn*32 + nb*16 + (sub >> 1)*8 + (lane & 7);
                ldsm4(bfr[nb], bB + swz(rn*128 + kk*32 + (sub & 1)*16));
            }
            #pragma unroll
            for (int mi = 0; mi < 4; ++mi)
                #pragma unroll
                for (int nb = 0; nb < 2; ++nb) {
                    mma16816(acc[mi][nb*2],     afr[mi], bfr[nb][0], bfr[nb][1]);
                    mma16816(acc[mi][nb*2 + 1], afr[mi], bfr[nb][2], bfr[nb][3]);
                }
        }
        __syncthreads();
    }

    const int quad = lane >> 2, tx2 = (lane & 3) * 2;
    #pragma unroll
    for (int mi = 0; mi < 4; ++mi) {
        #pragma unroll
        for (int n8 = 0; n8 < 4; ++n8) {
            int n = n0 + wn*32 + n8*8 + tx2;
            #pragma unroll
            for (int half = 0; half < 2; ++half) {
                int m = m0 + wm*64 + mi*16 + quad + half*8;
                float v0 = acc[mi][n8][half*2], v1 = acc[mi][n8][half*2 + 1];
                if constexpr (EPI == 2) {
                    float x0 = X[(size_t)m*H + (n & (H-1))];
                    float x1 = X[(size_t)m*H + ((n+1) & (H-1))];
                    v0 += x0*d2v[n]   + bias[n];
                    v1 += x1*d2v[n+1] + bias[n+1];
                    *reinterpret_cast<float2*>(&Cf[(size_t)m*Nld + n]) =
                        make_float2(v0, v1);
                } else {
                    __nv_bfloat16 h0 = __float2bfloat16(v0);
                    __nv_bfloat16 h1 = __float2bfloat16(v1);
                    __nv_bfloat162 hh{h0, h1};
                    __nv_bfloat162 ll{__float2bfloat16(v0 - __bfloat162float(h0)),
                                      __float2bfloat16(v1 - __bfloat162float(h1))};
                    __nv_bfloat16* rp = Pp + (size_t)m*(3*R) + n;
                    *reinterpret_cast<__nv_bfloat162*>(rp)         = hh;
                    *reinterpret_cast<__nv_bfloat162*>(rp + R)     = ll;
                    *reinterpret_cast<__nv_bfloat162*>(rp + 2*R)   = hh;
                }
            }
        }
    }
}

// ---------------------------------------------------------------------------
// persistent recurrent kernel
//   phase1: SIMT (unchanged) -> p' bf16 [hi|lo|hi] [64,768]
//   phase2: HMMA  G[64,32] = p'[64,768] @ w'[32,768]^T per CTA
// SMEM bytes: su fp32 0..65792 | red 65792..67840 | w' 67840..117504 (32x1552)
//             stage 117504..216832 (64x1552 bf16 / ph1 h-stage / kq partials)
// ---------------------------------------------------------------------------
constexpr int OFF_RED = 65792;
constexpr int OFF_W   = 67840;
constexpr int OFF_STG = 117504;
constexpr int SMEM_REC = 216832;
constexpr int WST = 1552;                      // padded row stride (bytes)

__global__ void __launch_bounds__(NTH, 1) lstm_rec(
    const float* __restrict__ c0, const float* __restrict__ h0,
    const float* __restrict__ u_h,
    const float* __restrict__ b_h, float* __restrict__ out, int full_out)
{
    extern __shared__ char smc[];
    float* su  = reinterpret_cast<float*>(smc);               // [16][1028]
    float* red = reinterpret_cast<float*>(smc + OFF_RED);     // [512]
    float* hst = reinterpret_cast<float*>(smc + OFF_STG);     // ph1 [8][1028]
    float* sp  = reinterpret_cast<float*>(smc + OFF_STG);     // ph2 partials [4][64][33]
    const uint32_t sb = smem_u32(smc);
    const uint32_t WB = sb + OFF_W, SB = sb + OFF_STG;

    const int tid = threadIdx.x, bk = blockIdx.x;
    const int rb = bk & 15, bb = bk >> 4;
    const int r_l = tid & 15, b_l = (tid >> 4) & 7, q = tid >> 7;
    const int jl2 = tid & 7, b2 = tid >> 3;
    const int j = bk * 8 + jl2;
    const int lane = tid & 31, wid = tid >> 5;
    const int mi = wid & 3, kq = wid >> 2;

    // persistent SMEM: u_h slice (fp32) + w' tile (bf16 packed)
    for (int i = tid; i < 16*1024; i += NTH) {
        int rl = i >> 10, d = i & 1023;
        su[rl*1028 + d] = u_h[(size_t)d*R + rb*16 + rl];
    }
    for (int i = tid; i < 32*96; i += NTH) {
        int row = i / 96, c8 = i - row*96;
        int wrow = (row >> 3) * H + bk * 8 + (row & 7);
        *reinterpret_cast<uint4*>(smc + OFF_W + row*WST + c8*16) =
            *reinterpret_cast<const uint4*>(g_Whp + (size_t)wrow*768 + c8*8);
    }

    float d2r[4], bhr[4];
    #pragma unroll
    for (int g = 0; g < 4; ++g) { d2r[g] = g_d2h[g*H + j]; bhr[g] = b_h[g*H + j]; }
    float hr = h0[b2*H + j];
    float cr = c0[b2*H + j];
    __syncthreads();

    unsigned bar = 0;
    for (int t = 0; t < T; ++t) {
        // prefetch gate inputs (DRAM) early — consumed in phase 2
        const float* gp = g_Gx + (size_t)t*(Bsz*G4H) + (size_t)b2*G4H + j;
        float gx0 = __ldcs(gp);
        float gx1 = __ldcs(gp + H);
        float gx2 = __ldcs(gp + 2*H);
        float gx3 = __ldcs(gp + 3*H);

        // ---- phase 1 (SIMT): p[8b,16r] = h[8b,:] @ u_h[:,16r] ----
        for (int i = tid; i < 8*256; i += NTH) {
            int row = i >> 8, c = i & 255;
            *reinterpret_cast<float4*>(&hst[row*1028 + c*4]) =
                __ldcg(reinterpret_cast<const float4*>(&g_h[(bb*8 + row)*H + c*4]));
        }
        __syncthreads();
        {
            unsigned long long a0 = 0ull, a1 = 0ull;
            const ulonglong2* hp = reinterpret_cast<const ulonglong2*>(&hst[b_l*1028 + q*256]);
            const ulonglong2* up = reinterpret_cast<const ulonglong2*>(&su[r_l*1028 + q*256]);
            #pragma unroll 8
            for (int k = 0; k < 64; ++k) {
                ulonglong2 hh = hp[k], uu = up[k];
                fma2(a0, hh.x, uu.x);
                fma2(a1, hh.y, uu.y);
            }
            float2 f0 = unpack2(a0), f1 = unpack2(a1);
            red[tid] = (f0.x + f0.y) + (f1.x + f1.y);
        }
        __syncthreads();
        if (tid < 128) {
            float s = red[tid] + red[tid+128] + red[tid+256] + red[tid+384];
            int b = bb*8 + (tid >> 4), r = rb*16 + (tid & 15);
            __nv_bfloat16 hi = __float2bfloat16(s);
            __nv_bfloat16 lo = __float2bfloat16(s - __bfloat162float(hi));
            g_pp[b*768 + r]       = hi;
            g_pp[b*768 + 256 + r] = lo;
            g_pp[b*768 + 512 + r] = hi;
        }
        bar += NB; gbar(bar);

        // ---- phase 2 (HMMA): G[64,32] = p'[64,768] @ w'[32,768]^T ----
        for (int i = tid; i < 64*96; i += NTH) {          // stage p' (L2, cp.async.cg)
            int row = i / 96, c8 = i - row*96;
            cp16(SB + row*WST + c8*16, g_pp + (size_t)row*768 + c8*8);
        }
        asm volatile("cp.async.commit_group;" ::: "memory");
        asm volatile("cp.async.wait_group 0;" ::: "memory");
        __syncthreads();

        float acc[4][4];
        #pragma unroll
        for (int a = 0; a < 4; ++a)
            #pragma unroll
            for (int b = 0; b < 4; ++b) acc[a][b] = 0.f;
        #pragma unroll
        for (int k16 = 0; k16 < 12; ++k16) {
            const int kb = kq*384 + k16*32;               // byte column offset
            uint32_t afr[4];
            ldsm4(afr, SB + (mi*16 + (lane & 15))*WST + kb + (lane >> 4)*16);
            uint32_t bfr[2][4];
            #pragma unroll
            for (int nb = 0; nb < 2; ++nb) {
                int sub = lane >> 3;
                int rn = nb*16 + (sub >> 1)*8 + (lane & 7);
                ldsm4(bfr[nb], WB + rn*WST + kb + (sub & 1)*16);
            }
            mma16816(acc[0], afr, bfr[0][0], bfr[0][1]);
            mma16816(acc[1], afr, bfr[0][2], bfr[0][3]);
            mma16816(acc[2], afr, bfr[1][0], bfr[1][1]);
            mma16816(acc[3], afr, bfr[1][2], bfr[1][3]);
        }
        __syncthreads();                                   // all reads of stage done
        {
            const int quad = lane >> 2, tx2 = (lane & 3)*2;
            const int m0r = mi*16 + quad;
            #pragma unroll
            for (int n8 = 0; n8 < 4; ++n8) {
                int n = n8*8 + tx2;
                sp[kq*2112 + m0r*33 + n]       = acc[n8][0];
                sp[kq*2112 + m0r*33 + n + 1]   = acc[n8][1];
                sp[kq*2112 + (m0r+8)*33 + n]   = acc[n8][2];
                sp[kq*2112 + (m0r+8)*33 + n+1] = acc[n8][3];
            }
        }
        __syncthreads();

        float s0 = 0.f, s1 = 0.f, s2 = 0.f, s3 = 0.f;
        #pragma unroll
        for (int kk = 0; kk < 4; ++kk) {
            const float* bp = sp + kk*2112 + b2*33;
            s0 += bp[jl2]; s1 += bp[8 + jl2]; s2 += bp[16 + jl2]; s3 += bp[24 + jl2];
        }
        float pi = s0 + hr*d2r[0] + bhr[0] + gx0;
        float pf = s1 + hr*d2r[1] + bhr[1] + gx1;
        float po = s2 + hr*d2r[2] + bhr[2] + gx2;
        float pn = s3 + hr*d2r[3] + bhr[3] + gx3;

        float ig = 1.f/(1.f+expf(-pi));
        float fg = 1.f/(1.f+expf(-pf));
        float og = 1.f/(1.f+expf(-po));
        float ng = tanhf(pn);
        cr = fg*cr + ig*ng;
        hr = og*tanhf(cr);

        __stcg(&g_h[b2*H + j], hr);
        __stcs(&out[(size_t)t*(Bsz*H) + b2*H + j], hr);
        if (t == T-1 && full_out) {
            out[(size_t)T*Bsz*H + b2*H + j]          = hr;
            out[(size_t)T*Bsz*H + Bsz*H + b2*H + j]  = cr;
        }
        bar += NB; gbar(bar);
    }
}

// ---------------------------------------------------------------------------
extern "C" void kernel_launch(void* const* d_in, const int* in_sizes, int n_in,
                              void* d_out, int out_size)
{
    const float* x     = (const float*)d_in[0];
    const float* h0    = (const float*)d_in[1];
    const float* c0    = (const float*)d_in[2];
    const float* u_x   = (const float*)d_in[3];
    const float* u_h   = (const float*)d_in[4];
    const float* w_x   = (const float*)d_in[5];
    const float* w_h   = (const float*)d_in[6];
    const float* b_x   = (const float*)d_in[7];
    const float* b_h   = (const float*)d_in[8];
    const float* dia_x = (const float*)d_in[9];
    const float* dia_h = (const float*)d_in[10];
    float* out = (float*)d_out;

    float *pGx=nullptr, *pd2x=nullptr;
    __nv_bfloat16 *pXp=nullptr, *pWp=nullptr, *pUp=nullptr, *pPp=nullptr, *pWhp=nullptr;
    cudaGetSymbolAddress((void**)&pGx,  g_Gx);
    cudaGetSymbolAddress((void**)&pd2x, g_d2x);
    cudaGetSymbolAddress((void**)&pXp,  g_Xp);
    cudaGetSymbolAddress((void**)&pWp,  g_Wp);
    cudaGetSymbolAddress((void**)&pUp,  g_Up);
    cudaGetSymbolAddress((void**)&pPp,  g_Pp);
    cudaGetSymbolAddress((void**)&pWhp, g_Whp);

    prep_kernel<<<32, 256>>>(u_x, w_x, dia_x, u_h, w_h, dia_h, h0);
    conv_pack<<<2048, 256>>>(x, pXp, 10, TB*D/4);     // X'  [TB, 3072]
    conv_wB  <<<512,  256>>>(w_x, pWp);               // Wx' [4096, 768]
    conv_wB  <<<512,  256>>>(w_h, pWhp);              // Wh' [4096, 768]
    conv_uT  <<<256,  256>>>(u_x, pUp);               // UxT'[256, 3072]

    cudaFuncSetAttribute(gemm_mma<1>, cudaFuncAttributeMaxDynamicSharedMemorySize, (int)GSM);
    cudaFuncSetAttribute(gemm_mma<2>, cudaFuncAttributeMaxDynamicSharedMemorySize, (int)GSM);

    // P' = X' @ UxT'^T  (M=16384, N=256, K'=3072) -> bf16 hi/lo/hi packed
    {
        dim3 grid(R/128, TB/128);
        gemm_mma<1><<<grid, 256, GSM>>>(pXp, pUp, 3*D, 0,
                                        nullptr, pPp, nullptr, nullptr, nullptr);
    }
    // Gx = P' @ Wx'^T + x*d2_x + b_x   (M=16384, N=4096, K'=768) -> fp32
    {
        dim3 grid(G4H/128, TB/128);
        gemm_mma<2><<<grid, 256, GSM>>>(pPp, pWp, 3*R, G4H,
                                        pGx, nullptr, x, pd2x, b_x);
    }
    cudaFuncSetAttribute(lstm_rec, cudaFuncAttributeMaxDynamicSharedMemorySize, SMEM_REC);
    int full_out = (out_size >= T*Bsz*H + 2*Bsz*H) ? 1 : 0;
    lstm_rec<<<NB, NTH, SMEM_REC>>>(c0, h0, u_h, b_h, out, full_out);
}

// round 13
// speedup vs baseline: 1.6627x; 1.0004x over previous
#include <cuda_runtime.h>
#include <cuda_bf16.h>
#include <cstdint>
#include <cstddef>

constexpr int T=256, Bsz=64, D=1024, H=1024, R=256;
constexpr int G4H=4*H, TB=T*Bsz, NB=128, NTH=512;

// static scratch (allocation-free)
__device__ __align__(256) __nv_bfloat16 g_Xp[(size_t)TB*3*D];    // X'  [TB, 3072]
__device__ __align__(256) __nv_bfloat16 g_Wp[(size_t)G4H*3*R];   // Wx' [4096, 768]
__device__ __align__(256) __nv_bfloat16 g_Up[(size_t)R*3*D];     // UxT'[256, 3072]
__device__ __align__(256) __nv_bfloat16 g_Pp[(size_t)TB*3*R];    // P'  [TB, 768]
__device__ __align__(256) __nv_bfloat16 g_Whp[(size_t)G4H*3*R];  // Wh' [4096, 768]
__device__ __align__(256) float g_pf[Bsz*R];                     // p fp32 per step
__device__ float g_Gx[(size_t)TB*G4H];
__device__ float g_d2x[G4H];
__device__ float g_d2h[G4H];
__device__ float g_h[Bsz*H];
__device__ unsigned g_count;

// ---------------- helpers ----------------
__device__ __forceinline__ void fma2(unsigned long long& acc,
                                     unsigned long long a, unsigned long long b) {
    asm("fma.rn.f32x2 %0, %1, %2, %0;" : "+l"(acc) : "l"(a), "l"(b));
}
__device__ __forceinline__ float2 unpack2(unsigned long long v) {
    float2 f; asm("mov.b64 {%0, %1}, %2;" : "=f"(f.x), "=f"(f.y) : "l"(v)); return f;
}
__device__ __forceinline__ uint32_t smem_u32(const void* p) {
    uint32_t a;
    asm("{ .reg .u64 t; cvta.to.shared.u64 t, %1; cvt.u32.u64 %0, t; }" : "=r"(a) : "l"(p));
    return a;
}
__device__ __forceinline__ void cp16(uint32_t dst, const void* src) {
    asm volatile("cp.async.cg.shared.global [%0], [%1], 16;" :: "r"(dst), "l"(src) : "memory");
}
__device__ __forceinline__ uint32_t swz(uint32_t o) { return o ^ ((o >> 3) & 0x70); }

__device__ __forceinline__ void ldsm4(uint32_t* r, uint32_t addr) {
    asm volatile("ldmatrix.sync.aligned.m8n8.x4.shared.b16 {%0,%1,%2,%3}, [%4];"
        : "=r"(r[0]), "=r"(r[1]), "=r"(r[2]), "=r"(r[3]) : "r"(addr));
}
__device__ __forceinline__ void mma16816(float* c, const uint32_t* a,
                                         uint32_t b0, uint32_t b1) {
    asm volatile(
        "mma.sync.aligned.m16n8k16.row.col.f32.bf16.bf16.f32 "
        "{%0,%1,%2,%3}, {%4,%5,%6,%7}, {%8,%9}, {%0,%1,%2,%3};"
        : "+f"(c[0]), "+f"(c[1]), "+f"(c[2]), "+f"(c[3])
        : "r"(a[0]), "r"(a[1]), "r"(a[2]), "r"(a[3]), "r"(b0), "r"(b1));
}

// ---------------- grid barrier (release/acquire, monotonic) ----------------
__device__ __forceinline__ void gbar(unsigned target) {
    __syncthreads();
    if (threadIdx.x == 0) {
        asm volatile("red.release.gpu.global.add.u32 [%0], 1;"
                     :: "l"(&g_count) : "memory");
        unsigned v;
        do {
            asm volatile("ld.acquire.gpu.global.u32 %0, [%1];"
                         : "=r"(v) : "l"(&g_count) : "memory");
        } while (v < target);
    }
    __syncthreads();
}

// ---------------- conversions ----------------
__global__ void conv_pack(const float* __restrict__ s, __nv_bfloat16* __restrict__ d,
                          int ls, int n4)
{
    const int rl = 1 << ls, mask = rl - 1;
    for (int i = blockIdx.x*blockDim.x + threadIdx.x; i < n4; i += gridDim.x*blockDim.x) {
        float4 v = reinterpret_cast<const float4*>(s)[i];
        int e = i * 4, m = e >> ls, col = e & mask;
        __nv_bfloat16 h0=__float2bfloat16(v.x), h1=__float2bfloat16(v.y);
        __nv_bfloat16 h2=__float2bfloat16(v.z), h3=__float2bfloat16(v.w);
        __nv_bfloat162 ha{h0,h1}, hb{h2,h3};
        __nv_bfloat162 la{__float2bfloat16(v.x-__bfloat162float(h0)),
                          __float2bfloat16(v.y-__bfloat162float(h1))};
        __nv_bfloat162 lb{__float2bfloat16(v.z-__bfloat162float(h2)),
                          __float2bfloat16(v.w-__bfloat162float(h3))};
        __nv_bfloat16* rp = d + (size_t)m*3*rl + col;
        reinterpret_cast<__nv_bfloat162*>(rp)[0]        = ha;
        reinterpret_cast<__nv_bfloat162*>(rp)[1]        = hb;
        reinterpret_cast<__nv_bfloat162*>(rp + rl)[0]   = la;
        reinterpret_cast<__nv_bfloat162*>(rp + rl)[1]   = lb;
        reinterpret_cast<__nv_bfloat162*>(rp + 2*rl)[0] = ha;
        reinterpret_cast<__nv_bfloat162*>(rp + 2*rl)[1] = hb;
    }
}
__global__ void conv_uT(const float* __restrict__ u, __nv_bfloat16* __restrict__ d)
{
    for (int i = blockIdx.x*blockDim.x + threadIdx.x; i < R*D; i += gridDim.x*blockDim.x) {
        int n = i >> 10, dd = i & 1023;
        float v = u[(size_t)dd*R + n];
        __nv_bfloat16 h = __float2bfloat16(v);
        __nv_bfloat16 l = __float2bfloat16(v - __bfloat162float(h));
        d[(size_t)n*3*D + dd]       = h;
        d[(size_t)n*3*D + D + dd]   = h;
        d[(size_t)n*3*D + 2*D + dd] = l;
    }
}
// rows of 256 fp32 -> rows of 768 bf16 [hi | hi | lo]
__global__ void conv_wB(const float* __restrict__ w, __nv_bfloat16* __restrict__ d)
{
    for (int i = blockIdx.x*blockDim.x + threadIdx.x; i < G4H*R/4; i += gridDim.x*blockDim.x) {
        float4 v = reinterpret_cast<const float4*>(w)[i];
        int e = i * 4, m = e >> 8, col = e & 255;
        __nv_bfloat16 h0=__float2bfloat16(v.x), h1=__float2bfloat16(v.y);
        __nv_bfloat16 h2=__float2bfloat16(v.z), h3=__float2bfloat16(v.w);
        __nv_bfloat162 ha{h0,h1}, hb{h2,h3};
        __nv_bfloat162 la{__float2bfloat16(v.x-__bfloat162float(h0)),
                          __float2bfloat16(v.y-__bfloat162float(h1))};
        __nv_bfloat162 lb{__float2bfloat16(v.z-__bfloat162float(h2)),
                          __float2bfloat16(v.w-__bfloat162float(h3))};
        __nv_bfloat16* rp = d + (size_t)m*3*R + col;
        reinterpret_cast<__nv_bfloat162*>(rp)[0]         = ha;
        reinterpret_cast<__nv_bfloat162*>(rp)[1]         = hb;
        reinterpret_cast<__nv_bfloat162*>(rp + R)[0]     = ha;
        reinterpret_cast<__nv_bfloat162*>(rp + R)[1]     = hb;
        reinterpret_cast<__nv_bfloat162*>(rp + 2*R)[0]   = la;
        reinterpret_cast<__nv_bfloat162*>(rp + 2*R)[1]   = lb;
    }
}

// ---------------- prep ----------------
__global__ void prep_kernel(const float* __restrict__ u_x, const float* __restrict__ w_x,
                            const float* __restrict__ dia_x,
                            const float* __restrict__ u_h, const float* __restrict__ w_h,
                            const float* __restrict__ dia_h, const float* __restrict__ h0)
{
    int n = blockIdx.x*blockDim.x + threadIdx.x;   // 0..8191
    if (n == 0) g_count = 0u;                      // barrier counter reset (replay-safe)
    const float *u, *w, *dia; float* o; int idx;
    if (n < G4H) { u=u_x; w=w_x; dia=dia_x; o=g_d2x; idx=n; }
    else         { u=u_h; w=w_h; dia=dia_h; o=g_d2h; idx=n-G4H; }
    int d = idx & (H-1);
    const float4* ur = reinterpret_cast<const float4*>(u + (size_t)d*R);
    const float4* wr = reinterpret_cast<const float4*>(w + (size_t)idx*R);
    float s = 0.f;
    #pragma unroll 8
    for (int k = 0; k < R/4; ++k) {
        float4 a = ur[k], b = wr[k];
        s += a.x*b.x + a.y*b.y + a.z*b.z + a.w*b.w;
    }
    o[idx] = dia[d] - s;
    for (int i = n; i < Bsz*H; i += 8192) g_h[i] = h0[i];
}

// ---------------------------------------------------------------------------
// HMMA GEMM for precompute (unchanged)
// ---------------------------------------------------------------------------
constexpr size_t GSM = 2*32768 + 1024;

template<int EPI>
__global__ void __launch_bounds__(256, 1) gemm_mma(
    const __nv_bfloat16* __restrict__ Ap, const __nv_bfloat16* __restrict__ Bp,
    int K, int Nld, float* __restrict__ Cf, __nv_bfloat16* __restrict__ Pp,
    const float* __restrict__ X, const float* __restrict__ d2v,
    const float* __restrict__ bias)
{
    extern __shared__ char smraw[];
    const uint32_t sb = (smem_u32(smraw) + 1023) & ~1023u;
    const int tid = threadIdx.x, lane = tid & 31, wid = tid >> 5;
    const int wm = wid >> 2, wn = wid & 3;
    const int m0 = blockIdx.y * 128, n0 = blockIdx.x * 128;

    const __nv_bfloat16* Asrc = Ap + (size_t)m0 * K;
    const __nv_bfloat16* Bsrc = Bp + (size_t)n0 * K;
    const int lrow = tid >> 3, lc8 = tid & 7;

    auto load_stage = [&](int kc, int s) {
        uint32_t base = sb + s * 32768;
        #pragma unroll
        for (int rr = 0; rr < 4; ++rr) {
            int row = lrow + rr * 32;
            cp16(base + swz(row*128 + lc8*16),
                 Asrc + (size_t)row*K + kc + lc8*8);
            cp16(base + 16384 + swz(row*128 + lc8*16),
                 Bsrc + (size_t)row*K + kc + lc8*8);
        }
        asm volatile("cp.async.commit_group;" ::: "memory");
    };

    float acc[4][4][4];
    #pragma unroll
    for (int a = 0; a < 4; ++a)
        #pragma unroll
        for (int b = 0; b < 4; ++b)
            #pragma unroll
            for (int c = 0; c < 4; ++c) acc[a][b][c] = 0.f;

    const int nIter = K / 64;
    load_stage(0, 0);
    for (int it = 0; it < nIter; ++it) {
        if (it + 1 < nIter) {
            load_stage((it + 1) * 64, (it + 1) & 1);
            asm volatile("cp.async.wait_group 1;" ::: "memory");
        } else {
            asm volatile("cp.async.wait_group 0;" ::: "memory");
        }
        __syncthreads();
        const uint32_t aB = sb + (it & 1) * 32768;
        const uint32_t bB = aB + 16384;
        #pragma unroll
        for (int kk = 0; kk < 4; ++kk) {
            uint32_t afr[4][4];
            #pragma unroll
            for (int mi = 0; mi < 4; ++mi) {
                int rowa = wm*64 + mi*16 + (lane & 15);
                ldsm4(afr[mi], aB + swz(rowa*128 + kk*32 + (lane >> 4)*16));
            }
            uint32_t bfr[2][4];
            #pragma unroll
            for (int nb = 0; nb < 2; ++nb) {
                int sub = lane >> 3;
                int rn = wn*32 + nb*16 + (sub >> 1)*8 + (lane & 7);
                ldsm4(bfr[nb], bB + swz(rn*128 + kk*32 + (sub & 1)*16));
            }
            #pragma unroll
            for (int mi = 0; mi < 4; ++mi)
                #pragma unroll
                for (int nb = 0; nb < 2; ++nb) {
                    mma16816(acc[mi][nb*2],     afr[mi], bfr[nb][0], bfr[nb][1]);
                    mma16816(acc[mi][nb*2 + 1], afr[mi], bfr[nb][2], bfr[nb][3]);
                }
        }
        __syncthreads();
    }

    const int quad = lane >> 2, tx2 = (lane & 3) * 2;
    #pragma unroll
    for (int mi = 0; mi < 4; ++mi) {
        #pragma unroll
        for (int n8 = 0; n8 < 4; ++n8) {
            int n = n0 + wn*32 + n8*8 + tx2;
            #pragma unroll
            for (int half = 0; half < 2; ++half) {
                int m = m0 + wm*64 + mi*16 + quad + half*8;
                float v0 = acc[mi][n8][half*2], v1 = acc[mi][n8][half*2 + 1];
                if constexpr (EPI == 2) {
                    float x0 = X[(size_t)m*H + (n & (H-1))];
                    float x1 = X[(size_t)m*H + ((n+1) & (H-1))];
                    v0 += x0*d2v[n]   + bias[n];
                    v1 += x1*d2v[n+1] + bias[n+1];
                    *reinterpret_cast<float2*>(&Cf[(size_t)m*Nld + n]) =
                        make_float2(v0, v1);
                } else {
                    __nv_bfloat16 h0 = __float2bfloat16(v0);
                    __nv_bfloat16 h1 = __float2bfloat16(v1);
                    __nv_bfloat162 hh{h0, h1};
                    __nv_bfloat162 ll{__float2bfloat16(v0 - __bfloat162float(h0)),
                                      __float2bfloat16(v1 - __bfloat162float(h1))};
                    __nv_bfloat16* rp = Pp + (size_t)m*(3*R) + n;
                    *reinterpret_cast<__nv_bfloat162*>(rp)         = hh;
                    *reinterpret_cast<__nv_bfloat162*>(rp + R)     = ll;
                    *reinterpret_cast<__nv_bfloat162*>(rp + 2*R)   = hh;
                }
            }
        }
    }
}

// ---------------------------------------------------------------------------
// persistent recurrent kernel
//   phase1: SIMT + shfl reduction -> p fp32 [64,256]
//   phase2: fp32->bf16 hi/lo staged A [64 x 1024B], B = Wh' [hi|hi|lo];
//           HMMA with aoff = kb & 1023 (3rd logical segment folds onto hi)
// SMEM: su 0..65792 | W 65792..115456 (32x1552) | stage 115456..182016
// ---------------------------------------------------------------------------
constexpr int OFF_W   = 65792;
constexpr int OFF_STG = 115456;
constexpr int SMEM_REC = 182016;
constexpr int WST  = 1552;                     // B row stride (bytes)
constexpr int AST  = 1040;                     // A row stride (bytes)

__global__ void __launch_bounds__(NTH, 1) lstm_rec(
    const float* __restrict__ c0, const float* __restrict__ h0,
    const float* __restrict__ u_h,
    const float* __restrict__ b_h, float* __restrict__ out, int full_out)
{
    extern __shared__ char smc[];
    float* su  = reinterpret_cast<float*>(smc);               // [16][1028]
    float* hst = reinterpret_cast<float*>(smc + OFF_STG);     // ph1 [8][1028]
    float* sp  = reinterpret_cast<float*>(smc + OFF_STG);     // ph2 partials [4][64][33]
    const uint32_t sb = smem_u32(smc);
    const uint32_t WB = sb + OFF_W, SB = sb + OFF_STG;

    const int tid = threadIdx.x, bk = blockIdx.x;
    const int rb = bk & 15, bb = bk >> 4;
    const int lane = tid & 31, wid = tid >> 5;
    // phase1 roles (shuffle reduction): widx=(warp,lane&7), q=lane>>3
    const int widx = wid*8 + (lane & 7);
    const int r_l = widx & 15, b_l = widx >> 4, q = lane >> 3;
    // phase2 roles
    const int jl2 = tid & 7, b2 = tid >> 3;
    const int j = bk * 8 + jl2;
    const int mi = wid & 3, kq = wid >> 2;

    // persistent SMEM: u_h slice (fp32) + Wh' tile (bf16 [hi|hi|lo])
    for (int i = tid; i < 16*1024; i += NTH) {
        int rl = i >> 10, d = i & 1023;
        su[rl*1028 + d] = u_h[(size_t)d*R + rb*16 + rl];
    }
    for (int i = tid; i < 32*96; i += NTH) {
        int row = i / 96, c8 = i - row*96;
        int wrow = (row >> 3) * H + bk * 8 + (row & 7);
        *reinterpret_cast<uint4*>(smc + OFF_W + row*WST + c8*16) =
            *reinterpret_cast<const uint4*>(g_Whp + (size_t)wrow*768 + c8*8);
    }

    float d2r[4], bhr[4];
    #pragma unroll
    for (int g = 0; g < 4; ++g) { d2r[g] = g_d2h[g*H + j]; bhr[g] = b_h[g*H + j]; }
    float hr = h0[b2*H + j];
    float cr = c0[b2*H + j];
    __syncthreads();

    unsigned bar = 0;
    for (int t = 0; t < T; ++t) {
        // prefetch gate inputs (DRAM) early — consumed in phase 2
        const float* gp = g_Gx + (size_t)t*(Bsz*G4H) + (size_t)b2*G4H + j;
        float gx0 = __ldcs(gp);
        float gx1 = __ldcs(gp + H);
        float gx2 = __ldcs(gp + 2*H);
        float gx3 = __ldcs(gp + 3*H);

        // ---- phase 1 (SIMT): p[8b,16r] = h[8b,:] @ u_h[:,16r] ----
        for (int i = tid; i < 8*256; i += NTH) {
            int row = i >> 8, c = i & 255;
            *reinterpret_cast<float4*>(&hst[row*1028 + c*4]) =
                __ldcg(reinterpret_cast<const float4*>(&g_h[(bb*8 + row)*H + c*4]));
        }
        __syncthreads();
        {
            unsigned long long a0 = 0ull, a1 = 0ull;
            const ulonglong2* hp = reinterpret_cast<const ulonglong2*>(&hst[b_l*1028 + q*256]);
            const ulonglong2* up = reinterpret_cast<const ulonglong2*>(&su[r_l*1028 + q*256]);
            #pragma unroll 8
            for (int k = 0; k < 64; ++k) {
                ulonglong2 hh = hp[k], uu = up[k];
                fma2(a0, hh.x, uu.x);
                fma2(a1, hh.y, uu.y);
            }
            float2 f0 = unpack2(a0), f1 = unpack2(a1);
            float s = (f0.x + f0.y) + (f1.x + f1.y);
            s += __shfl_xor_sync(0xffffffffu, s, 8);
            s += __shfl_xor_sync(0xffffffffu, s, 16);
            if ((lane & 31) < 8) {
                int b = bb*8 + b_l, r = rb*16 + r_l;
                __stcg(&g_pf[b*R + r], s);
            }
        }
        bar += NB; gbar(bar);

        // ---- phase 2 (HMMA): stage p fp32 -> bf16 [hi|lo] in SMEM ----
        for (int i = tid; i < 64*64; i += NTH) {          // 64 rows x 64 float4
            int row = i >> 6, c4 = i & 63;
            float4 v = __ldcg(reinterpret_cast<const float4*>(g_pf) + i);
            __nv_bfloat162 hA{__float2bfloat16(v.x), __float2bfloat16(v.y)};
            __nv_bfloat162 hB{__float2bfloat16(v.z), __float2bfloat16(v.w)};
            __nv_bfloat162 lA{__float2bfloat16(v.x-__bfloat162float(hA.x)),
                              __float2bfloat16(v.y-__bfloat162float(hA.y))};
            __nv_bfloat162 lB{__float2bfloat16(v.z-__bfloat162float(hB.x)),
                              __float2bfloat16(v.w-__bfloat162float(hB.y))};
            char* rp = smc + OFF_STG + row*AST + c4*8;
            *reinterpret_cast<__nv_bfloat162*>(rp)           = hA;
            *reinterpret_cast<__nv_bfloat162*>(rp + 4)       = hB;
            *reinterpret_cast<__nv_bfloat162*>(rp + 512)     = lA;
            *reinterpret_cast<__nv_bfloat162*>(rp + 516)     = lB;
        }
        __syncthreads();

        float acc[4][4];
        #pragma unroll
        for (int a = 0; a < 4; ++a)
            #pragma unroll
            for (int b = 0; b < 4; ++b) acc[a][b] = 0.f;
        #pragma unroll
        for (int k16 = 0; k16 < 12; ++k16) {
            const int kb = kq*384 + k16*32;               // logical byte column
            const int aoff = kb & 1023;                   // [hi|lo|hi] -> [hi|lo]
            uint32_t afr[4];
            ldsm4(afr, SB + (mi*16 + (lane & 15))*AST + aoff + (lane >> 4)*16);
            uint32_t bfr[2][4];
            #pragma unroll
            for (int nb = 0; nb < 2; ++nb) {
                int sub = lane >> 3;
                int rn = nb*16 + (sub >> 1)*8 + (lane & 7);
                ldsm4(bfr[nb], WB + rn*WST + kb + (sub & 1)*16);
            }
            mma16816(acc[0], afr, bfr[0][0], bfr[0][1]);
            mma16816(acc[1], afr, bfr[0][2], bfr[0][3]);
            mma16816(acc[2], afr, bfr[1][0], bfr[1][1]);
            mma16816(acc[3], afr, bfr[1][2], bfr[1][3]);
        }
        __syncthreads();                                   // stage reads done
        {
            const int quad = lane >> 2, tx2 = (lane & 3)*2;
            const int m0r = mi*16 + quad;
            #pragma unroll
            for (int n8 = 0; n8 < 4; ++n8) {
                int n = n8*8 + tx2;
                sp[kq*2112 + m0r*33 + n]       = acc[n8][0];
                sp[kq*2112 + m0r*33 + n + 1]   = acc[n8][1];
                sp[kq*2112 + (m0r+8)*33 + n]   = acc[n8][2];
                sp[kq*2112 + (m0r+8)*33 + n+1] = acc[n8][3];
            }
        }
        __syncthreads();

        float s0 = 0.f, s1 = 0.f, s2 = 0.f, s3 = 0.f;
        #pragma unroll
        for (int kk = 0; kk < 4; ++kk) {
            const float* bp = sp + kk*2112 + b2*33;
            s0 += bp[jl2]; s1 += bp[8 + jl2]; s2 += bp[16 + jl2]; s3 += bp[24 + jl2];
        }
        float pi = s0 + hr*d2r[0] + bhr[0] + gx0;
        float pf = s1 + hr*d2r[1] + bhr[1] + gx1;
        float po = s2 + hr*d2r[2] + bhr[2] + gx2;
        float pn = s3 + hr*d2r[3] + bhr[3] + gx3;

        float ig = 1.f/(1.f+expf(-pi));
        float fg = 1.f/(1.f+expf(-pf));
        float og = 1.f/(1.f+expf(-po));
        float ng = tanhf(pn);
        cr = fg*cr + ig*ng;
        hr = og*tanhf(cr);

        __stcg(&g_h[b2*H + j], hr);                        // consumed next step
        bar += NB; gbar(bar);
        // out stores AFTER barrier: off the release-ordering critical path
        __stcs(&out[(size_t)t*(Bsz*H) + b2*H + j], hr);
        if (t == T-1 && full_out) {
            out[(size_t)T*Bsz*H + b2*H + j]          = hr;
            out[(size_t)T*Bsz*H + Bsz*H + b2*H + j]  = cr;
        }
    }
}

// ---------------------------------------------------------------------------
extern "C" void kernel_launch(void* const* d_in, const int* in_sizes, int n_in,
                              void* d_out, int out_size)
{
    const float* x     = (const float*)d_in[0];
    const float* h0    = (const float*)d_in[1];
    const float* c0    = (const float*)d_in[2];
    const float* u_x   = (const float*)d_in[3];
    const float* u_h   = (const float*)d_in[4];
    const float* w_x   = (const float*)d_in[5];
    const float* w_h   = (const float*)d_in[6];
    const float* b_x   = (const float*)d_in[7];
    const float* b_h   = (const float*)d_in[8];
    const float* dia_x = (const float*)d_in[9];
    const float* dia_h = (const float*)d_in[10];
    float* out = (float*)d_out;

    float *pGx=nullptr, *pd2x=nullptr;
    __nv_bfloat16 *pXp=nullptr, *pWp=nullptr, *pUp=nullptr, *pPp=nullptr, *pWhp=nullptr;
    cudaGetSymbolAddress((void**)&pGx,  g_Gx);
    cudaGetSymbolAddress((void**)&pd2x, g_d2x);
    cudaGetSymbolAddress((void**)&pXp,  g_Xp);
    cudaGetSymbolAddress((void**)&pWp,  g_Wp);
    cudaGetSymbolAddress((void**)&pUp,  g_Up);
    cudaGetSymbolAddress((void**)&pPp,  g_Pp);
    cudaGetSymbolAddress((void**)&pWhp, g_Whp);

    prep_kernel<<<32, 256>>>(u_x, w_x, dia_x, u_h, w_h, dia_h, h0);
    conv_pack<<<2048, 256>>>(x, pXp, 10, TB*D/4);     // X'  [TB, 3072]
    conv_wB  <<<512,  256>>>(w_x, pWp);               // Wx' [4096, 768]
    conv_wB  <<<512,  256>>>(w_h, pWhp);              // Wh' [4096, 768]
    conv_uT  <<<256,  256>>>(u_x, pUp);               // UxT'[256, 3072]

    cudaFuncSetAttribute(gemm_mma<1>, cudaFuncAttributeMaxDynamicSharedMemorySize, (int)GSM);
    cudaFuncSetAttribute(gemm_mma<2>, cudaFuncAttributeMaxDynamicSharedMemorySize, (int)GSM);

    // P' = X' @ UxT'^T  (M=16384, N=256, K'=3072) -> bf16 hi/lo/hi packed
    {
        dim3 grid(R/128, TB/128);
        gemm_mma<1><<<grid, 256, GSM>>>(pXp, pUp, 3*D, 0,
                                        nullptr, pPp, nullptr, nullptr, nullptr);
    }
    // Gx = P' @ Wx'^T + x*d2_x + b_x   (M=16384, N=4096, K'=768) -> fp32
    {
        dim3 grid(G4H/128, TB/128);
        gemm_mma<2><<<grid, 256, GSM>>>(pPp, pWp, 3*R, G4H,
                                        pGx, nullptr, x, pd2x, b_x);
    }
    cudaFuncSetAttribute(lstm_rec, cudaFuncAttributeMaxDynamicSharedMemorySize, SMEM_REC);
    int full_out = (out_size >= T*Bsz*H + 2*Bsz*H) ? 1 : 0;
    lstm_rec<<<NB, NTH, SMEM_REC>>>(c0, h0, u_h, b_h, out, full_out);
}